// round 1
// baseline (speedup 1.0000x reference)
#include <cuda_runtime.h>
#include <math.h>

#define D_MODEL 1024
#define T_SEQ   2048
#define BATCH   2
#define NTOK    (BATCH * T_SEQ)   // 4096 rows
#define D_FF    4096
#define NH      16
#define DH      64

// ---------------- scratch (no allocations allowed) ----------------
__device__ float g_xn  [NTOK * D_MODEL];
__device__ float g_q   [NTOK * D_MODEL];
__device__ float g_k   [NTOK * D_MODEL];
__device__ float g_v   [NTOK * D_MODEL];
__device__ float g_attn[NTOK * D_MODEL];
__device__ float g_x2  [NTOK * D_MODEL];
__device__ float g_h   [NTOK * D_MODEL];
__device__ float g_f1  [NTOK * D_FF];

// ---------------- RMSNorm: one block per row ----------------
__global__ void __launch_bounds__(256) rmsnorm_kernel(
    const float* __restrict__ x, const float* __restrict__ g, float* __restrict__ y)
{
    int row = blockIdx.x;
    int tid = threadIdx.x;
    const float4* xr = (const float4*)(x + (size_t)row * D_MODEL);
    float4 v = xr[tid];
    float s = v.x * v.x + v.y * v.y + v.z * v.z + v.w * v.w;
    #pragma unroll
    for (int o = 16; o > 0; o >>= 1) s += __shfl_xor_sync(0xffffffffu, s, o);
    __shared__ float red[8];
    if ((tid & 31) == 0) red[tid >> 5] = s;
    __syncthreads();
    float tot = red[0] + red[1] + red[2] + red[3] + red[4] + red[5] + red[6] + red[7];
    float inv = rsqrtf(tot * (1.0f / D_MODEL) + 1e-6f);
    float4 gv = ((const float4*)g)[tid];
    float4 o4;
    o4.x = v.x * inv * gv.x; o4.y = v.y * inv * gv.y;
    o4.z = v.z * inv * gv.z; o4.w = v.w * inv * gv.w;
    ((float4*)(y + (size_t)row * D_MODEL))[tid] = o4;
}

// ---------------- 128x128x16 SGEMM, 8x8 per thread, fused epilogue ----------------
template<bool BIAS, bool GELU_ACT, bool RES>
__global__ void __launch_bounds__(256) gemm_kernel(
    const float* __restrict__ A, const float* __restrict__ B,
    const float* __restrict__ bias, const float* __restrict__ res,
    float* __restrict__ C, int M, int N, int K)
{
    __shared__ float As[16][128];   // A transposed: As[k][m]
    __shared__ float Bs[16][128];   // Bs[k][n]
    int tid = threadIdx.x;
    int tx = tid & 15, ty = tid >> 4;
    int bm = blockIdx.y, bn = blockIdx.x;
    const float* Ab = A + (size_t)bm * 128 * K;
    const float* Bb = B + (size_t)bn * 128;

    float acc[8][8];
    #pragma unroll
    for (int i = 0; i < 8; i++)
        #pragma unroll
        for (int j = 0; j < 8; j++) acc[i][j] = 0.f;

    for (int k0 = 0; k0 < K; k0 += 16) {
        #pragma unroll
        for (int t = 0; t < 2; t++) {
            int f  = tid + t * 256;          // 0..511 float4s of A tile
            int ar = f >> 2;                 // row in tile (0..127)
            int ac = (f & 3) << 2;           // k-col (0,4,8,12)
            float4 v = *(const float4*)(Ab + (size_t)ar * K + k0 + ac);
            As[ac + 0][ar] = v.x; As[ac + 1][ar] = v.y;
            As[ac + 2][ar] = v.z; As[ac + 3][ar] = v.w;
        }
        #pragma unroll
        for (int t = 0; t < 2; t++) {
            int f  = tid + t * 256;
            int br = f >> 5;                 // k-row 0..15
            int bc = (f & 31) << 2;          // n-col 0..124
            float4 v = *(const float4*)(Bb + (size_t)(k0 + br) * N + bc);
            *(float4*)&Bs[br][bc] = v;
        }
        __syncthreads();
        #pragma unroll
        for (int kk = 0; kk < 16; kk++) {
            float a[8], bb[8];
            #pragma unroll
            for (int i = 0; i < 4; i++) {
                a[i]     = As[kk][ty * 4 + i];
                a[i + 4] = As[kk][64 + ty * 4 + i];
            }
            #pragma unroll
            for (int j = 0; j < 4; j++) {
                bb[j]     = Bs[kk][tx * 4 + j];
                bb[j + 4] = Bs[kk][64 + tx * 4 + j];
            }
            #pragma unroll
            for (int i = 0; i < 8; i++)
                #pragma unroll
                for (int j = 0; j < 8; j++)
                    acc[i][j] = fmaf(a[i], bb[j], acc[i][j]);
        }
        __syncthreads();
    }

    #pragma unroll
    for (int i = 0; i < 8; i++) {
        int r = bm * 128 + ((i < 4) ? (ty * 4 + i) : (64 + ty * 4 + i - 4));
        #pragma unroll
        for (int j = 0; j < 8; j++) {
            int c = bn * 128 + ((j < 4) ? (tx * 4 + j) : (64 + tx * 4 + j - 4));
            float vv = acc[i][j];
            if (BIAS) vv += bias[c];
            if (GELU_ACT) vv = 0.5f * vv * (1.0f + erff(vv * 0.70710678118654752f));
            size_t idx = (size_t)r * N + c;
            if (RES) vv += res[idx];
            C[idx] = vv;
        }
    }
}

// ---------------- causal flash attention, 64x64 tiles, fp32 SIMT ----------------
// q,k,v,o layout: [(b*T + t) * D_MODEL + h*DH + d]
__global__ void __launch_bounds__(256) attn_kernel(
    const float* __restrict__ q, const float* __restrict__ k,
    const float* __restrict__ v, float* __restrict__ o)
{
    __shared__ float Qs [64 * 64];   // Q[r][d], pre-scaled by 1/sqrt(Dh)
    __shared__ float KPs[64 * 64];   // phase1: K rot-swizzled K[d][c]; phase2: P[r][c]
    __shared__ float Vs [64 * 64];   // V[c][d]
    int qb = blockIdx.x, h = blockIdx.y, b = blockIdx.z;
    int tid = threadIdx.x;
    int tx = tid & 15, ty = tid >> 4;
    size_t base = (size_t)b * T_SEQ * D_MODEL + h * DH;

    for (int f = tid; f < 64 * 16; f += 256) {
        int r  = f >> 4;
        int d0 = (f & 15) << 2;
        float4 val = *(const float4*)(q + base + (size_t)(qb * 64 + r) * D_MODEL + d0);
        Qs[r * 64 + d0 + 0] = val.x * 0.125f;
        Qs[r * 64 + d0 + 1] = val.y * 0.125f;
        Qs[r * 64 + d0 + 2] = val.z * 0.125f;
        Qs[r * 64 + d0 + 3] = val.w * 0.125f;
    }

    float m_[4], l_[4], oacc[4][4];
    #pragma unroll
    for (int i = 0; i < 4; i++) {
        m_[i] = -1e30f; l_[i] = 0.f;
        #pragma unroll
        for (int j = 0; j < 4; j++) oacc[i][j] = 0.f;
    }

    for (int kb = 0; kb <= qb; kb++) {
        // load K (rotation swizzle: KPs[d*64 + (c+d)&63]) and V
        for (int f = tid; f < 64 * 16; f += 256) {
            int r  = f >> 4;
            int d0 = (f & 15) << 2;
            float4 kv = *(const float4*)(k + base + (size_t)(kb * 64 + r) * D_MODEL + d0);
            KPs[(d0 + 0) * 64 + ((r + d0 + 0) & 63)] = kv.x;
            KPs[(d0 + 1) * 64 + ((r + d0 + 1) & 63)] = kv.y;
            KPs[(d0 + 2) * 64 + ((r + d0 + 2) & 63)] = kv.z;
            KPs[(d0 + 3) * 64 + ((r + d0 + 3) & 63)] = kv.w;
            float4 vv = *(const float4*)(v + base + (size_t)(kb * 64 + r) * D_MODEL + d0);
            *(float4*)&Vs[r * 64 + d0] = vv;
        }
        __syncthreads();

        // S = Q K^T  (4x4 per thread)
        float s[4][4];
        #pragma unroll
        for (int i = 0; i < 4; i++)
            #pragma unroll
            for (int j = 0; j < 4; j++) s[i][j] = 0.f;
        for (int d = 0; d < 64; d++) {
            float qr[4], kr[4];
            #pragma unroll
            for (int i = 0; i < 4; i++) qr[i] = Qs[(ty * 4 + i) * 64 + d];
            #pragma unroll
            for (int j = 0; j < 4; j++) kr[j] = KPs[d * 64 + ((tx * 4 + j + d) & 63)];
            #pragma unroll
            for (int i = 0; i < 4; i++)
                #pragma unroll
                for (int j = 0; j < 4; j++)
                    s[i][j] = fmaf(qr[i], kr[j], s[i][j]);
        }
        if (kb == qb) {
            #pragma unroll
            for (int i = 0; i < 4; i++)
                #pragma unroll
                for (int j = 0; j < 4; j++)
                    if (tx * 4 + j > ty * 4 + i) s[i][j] = -1e30f;
        }

        // online softmax (row groups of 16 lanes)
        #pragma unroll
        for (int i = 0; i < 4; i++) {
            float rm = fmaxf(fmaxf(s[i][0], s[i][1]), fmaxf(s[i][2], s[i][3]));
            #pragma unroll
            for (int off = 8; off > 0; off >>= 1)
                rm = fmaxf(rm, __shfl_xor_sync(0xffffffffu, rm, off, 16));
            float mn    = fmaxf(m_[i], rm);
            float alpha = __expf(m_[i] - mn);
            float rs = 0.f;
            #pragma unroll
            for (int j = 0; j < 4; j++) { s[i][j] = __expf(s[i][j] - mn); rs += s[i][j]; }
            #pragma unroll
            for (int off = 8; off > 0; off >>= 1)
                rs += __shfl_xor_sync(0xffffffffu, rs, off, 16);
            l_[i] = l_[i] * alpha + rs;
            m_[i] = mn;
            #pragma unroll
            for (int j = 0; j < 4; j++) oacc[i][j] *= alpha;
        }
        __syncthreads();

        // write P into KPs (plain [r][c] layout)
        #pragma unroll
        for (int i = 0; i < 4; i++)
            #pragma unroll
            for (int j = 0; j < 4; j++)
                KPs[(ty * 4 + i) * 64 + tx * 4 + j] = s[i][j];
        __syncthreads();

        // O += P @ V
        for (int kk = 0; kk < 64; kk++) {
            float p[4], vv[4];
            #pragma unroll
            for (int i = 0; i < 4; i++) p[i] = KPs[(ty * 4 + i) * 64 + kk];
            #pragma unroll
            for (int j = 0; j < 4; j++) vv[j] = Vs[kk * 64 + tx * 4 + j];
            #pragma unroll
            for (int i = 0; i < 4; i++)
                #pragma unroll
                for (int j = 0; j < 4; j++)
                    oacc[i][j] = fmaf(p[i], vv[j], oacc[i][j]);
        }
        __syncthreads();
    }

    #pragma unroll
    for (int i = 0; i < 4; i++) {
        float invl = 1.f / l_[i];
        size_t rowbase = base + (size_t)(qb * 64 + ty * 4 + i) * D_MODEL + tx * 4;
        #pragma unroll
        for (int j = 0; j < 4; j++)
            o[rowbase + j] = oacc[i][j] * invl;
    }
}

// ---------------- launch ----------------
extern "C" void kernel_launch(void* const* d_in, const int* in_sizes, int n_in,
                              void* d_out, int out_size)
{
    const float* x  = (const float*)d_in[0];
    const float* Wq = (const float*)d_in[1];
    const float* Wk = (const float*)d_in[2];
    const float* Wv = (const float*)d_in[3];
    const float* Wo = (const float*)d_in[4];
    const float* W1 = (const float*)d_in[5];
    const float* b1 = (const float*)d_in[6];
    const float* W2 = (const float*)d_in[7];
    const float* b2 = (const float*)d_in[8];
    const float* g1 = (const float*)d_in[9];
    const float* g2 = (const float*)d_in[10];
    float* out = (float*)d_out;

    float *xn, *qp, *kp, *vp, *attn, *x2, *hn, *f1;
    cudaGetSymbolAddress((void**)&xn,   g_xn);
    cudaGetSymbolAddress((void**)&qp,   g_q);
    cudaGetSymbolAddress((void**)&kp,   g_k);
    cudaGetSymbolAddress((void**)&vp,   g_v);
    cudaGetSymbolAddress((void**)&attn, g_attn);
    cudaGetSymbolAddress((void**)&x2,   g_x2);
    cudaGetSymbolAddress((void**)&hn,   g_h);
    cudaGetSymbolAddress((void**)&f1,   g_f1);

    dim3 gproj(D_MODEL / 128, NTOK / 128);   // (8, 32)
    dim3 gffn1(D_FF   / 128, NTOK / 128);    // (32, 32)

    // x1 = rmsnorm(x, g1)
    rmsnorm_kernel<<<NTOK, 256>>>(x, g1, xn);
    // q/k/v projections
    gemm_kernel<false, false, false><<<gproj, 256>>>(xn, Wq, nullptr, nullptr, qp, NTOK, D_MODEL, D_MODEL);
    gemm_kernel<false, false, false><<<gproj, 256>>>(xn, Wk, nullptr, nullptr, kp, NTOK, D_MODEL, D_MODEL);
    gemm_kernel<false, false, false><<<gproj, 256>>>(xn, Wv, nullptr, nullptr, vp, NTOK, D_MODEL, D_MODEL);
    // causal attention
    attn_kernel<<<dim3(T_SEQ / 64, NH, BATCH), 256>>>(qp, kp, vp, attn);
    // x2 = x + attn @ Wo
    gemm_kernel<false, false, true><<<gproj, 256>>>(attn, Wo, nullptr, x, x2, NTOK, D_MODEL, D_MODEL);
    // h = rmsnorm(x2, g2)
    rmsnorm_kernel<<<NTOK, 256>>>(x2, g2, hn);
    // f1 = gelu(h @ W1 + b1)
    gemm_kernel<true, true, false><<<gffn1, 256>>>(hn, W1, b1, nullptr, f1, NTOK, D_FF, D_MODEL);
    // out = x2 + f1 @ W2 + b2
    gemm_kernel<true, false, true><<<gproj, 256>>>(f1, W2, b2, x2, out, NTOK, D_MODEL, D_FF);
}

// round 3
// speedup vs baseline: 1.9402x; 1.9402x over previous
#include <cuda_runtime.h>
#include <math.h>
#include <cstdint>

#define D_MODEL 1024
#define T_SEQ   2048
#define BATCH   2
#define NTOK    (BATCH * T_SEQ)   // 4096
#define D_FF    4096
#define NH      16
#define DH      64
#define QKV_N   3072

// ---------------- scratch (no allocations allowed) ----------------
__device__ float g_xn   [NTOK * D_MODEL];
__device__ float g_qkv  [NTOK * QKV_N];
__device__ float g_attn [NTOK * D_MODEL];
__device__ float g_x2   [NTOK * D_MODEL];
__device__ float g_h    [NTOK * D_MODEL];
__device__ float g_f1   [NTOK * D_FF];
__device__ float g_wqkvT[QKV_N * D_MODEL];
__device__ float g_woT  [D_MODEL * D_MODEL];
__device__ float g_w1T  [D_FF * D_MODEL];
__device__ float g_w2T  [D_MODEL * D_FF];

__device__ __forceinline__ uint32_t f2tf32(float x) {
    uint32_t r; asm("cvt.rna.tf32.f32 %0, %1;" : "=r"(r) : "f"(x)); return r;
}

// ---------------- weight transpose + tf32 round: W[K][N] -> WT[N][K] ----------------
__global__ void __launch_bounds__(256) transpose_round(
    const float* __restrict__ W, float* __restrict__ WT, int K, int N)
{
    __shared__ float t[32][33];
    int n0 = blockIdx.x * 32, k0 = blockIdx.y * 32;
    int tx = threadIdx.x & 31, ty = threadIdx.x >> 5;   // 32x8
    #pragma unroll
    for (int i = 0; i < 32; i += 8)
        t[ty + i][tx] = W[(size_t)(k0 + ty + i) * N + n0 + tx];
    __syncthreads();
    #pragma unroll
    for (int i = 0; i < 32; i += 8)
        WT[(size_t)(n0 + ty + i) * K + k0 + tx] = __uint_as_float(f2tf32(t[tx][ty + i]));
}

// ---------------- RMSNorm ----------------
__global__ void __launch_bounds__(256) rmsnorm_kernel(
    const float* __restrict__ x, const float* __restrict__ g, float* __restrict__ y)
{
    int row = blockIdx.x;
    int tid = threadIdx.x;
    const float4* xr = (const float4*)(x + (size_t)row * D_MODEL);
    float4 v = xr[tid];
    float s = v.x * v.x + v.y * v.y + v.z * v.z + v.w * v.w;
    #pragma unroll
    for (int o = 16; o > 0; o >>= 1) s += __shfl_xor_sync(0xffffffffu, s, o);
    __shared__ float red[8];
    if ((tid & 31) == 0) red[tid >> 5] = s;
    __syncthreads();
    float tot = red[0] + red[1] + red[2] + red[3] + red[4] + red[5] + red[6] + red[7];
    float inv = rsqrtf(tot * (1.0f / D_MODEL) + 1e-6f);
    float4 gv = ((const float4*)g)[tid];
    float4 o4;
    o4.x = v.x * inv * gv.x; o4.y = v.y * inv * gv.y;
    o4.z = v.z * inv * gv.z; o4.w = v.w * inv * gv.w;
    ((float4*)(y + (size_t)row * D_MODEL))[tid] = o4;
}

// ---------------- tf32 mma.sync GEMM: C[M,N] = A[M,K] @ BT[N,K]^T ----------------
// Block tile 128x128, 8 warps (2M x 4N), warp tile 64x32 = 4x4 m16n8k8 MMAs.
// K-chunks of 32, double-buffered SMEM (stride 36 floats -> conflict-free frags).
#define SM_STRIDE 36
#define SM_TILE   (128 * SM_STRIDE)   // floats per buffer per operand

template<bool BIAS, bool GELU_ACT, bool RES>
__global__ void __launch_bounds__(256) gemm_mma(
    const float* __restrict__ A, const float* __restrict__ BT,
    const float* __restrict__ bias, const float* __restrict__ res,
    float* __restrict__ C, int M, int N, int K)
{
    extern __shared__ float sm[];
    float* As = sm;                    // 2 buffers
    float* Bs = sm + 2 * SM_TILE;      // 2 buffers

    int tid = threadIdx.x;
    int lane = tid & 31, wid = tid >> 5;
    int warpM = (wid & 1) * 64;        // 2 warps in M
    int warpN = (wid >> 1) * 32;       // 4 warps in N
    int grp = lane >> 2, tig = lane & 3;
    int bn = blockIdx.x, bm = blockIdx.y;

    const float* Ab = A  + (size_t)bm * 128 * K;
    const float* Bb = BT + (size_t)bn * 128 * K;

    // per-thread gmem load coords (4 float4 per operand per chunk)
    int ldr = tid >> 3;                // 0..31 base row step 32
    int ldc = (tid & 7) << 2;          // k-offset 0..28

    float acc[4][4][4];
    #pragma unroll
    for (int mi = 0; mi < 4; mi++)
        #pragma unroll
        for (int ni = 0; ni < 4; ni++)
            #pragma unroll
            for (int r = 0; r < 4; r++) acc[mi][ni][r] = 0.f;

    int nch = K >> 5;
    float4 sa[4], sb[4];

    // prologue: load chunk 0
    #pragma unroll
    for (int t = 0; t < 4; t++) {
        sa[t] = *(const float4*)(Ab + (size_t)(ldr + t * 32) * K + ldc);
        sb[t] = *(const float4*)(Bb + (size_t)(ldr + t * 32) * K + ldc);
    }
    #pragma unroll
    for (int t = 0; t < 4; t++) {
        float* pa = &As[(ldr + t * 32) * SM_STRIDE + ldc];
        pa[0] = __uint_as_float(f2tf32(sa[t].x));
        pa[1] = __uint_as_float(f2tf32(sa[t].y));
        pa[2] = __uint_as_float(f2tf32(sa[t].z));
        pa[3] = __uint_as_float(f2tf32(sa[t].w));
        *(float4*)&Bs[(ldr + t * 32) * SM_STRIDE + ldc] = sb[t];
    }
    __syncthreads();

    for (int c = 0; c < nch; c++) {
        int buf = c & 1;
        if (c + 1 < nch) {
            int k0 = (c + 1) << 5;
            #pragma unroll
            for (int t = 0; t < 4; t++) {
                sa[t] = *(const float4*)(Ab + (size_t)(ldr + t * 32) * K + k0 + ldc);
                sb[t] = *(const float4*)(Bb + (size_t)(ldr + t * 32) * K + k0 + ldc);
            }
        }
        const float* Asb = &As[buf * SM_TILE];
        const float* Bsb = &Bs[buf * SM_TILE];
        #pragma unroll
        for (int kk = 0; kk < 4; kk++) {
            int k8 = kk << 3;
            uint32_t af[4][4], bf[4][2];
            #pragma unroll
            for (int mi = 0; mi < 4; mi++) {
                const float* p0 = &Asb[(warpM + mi * 16 + grp) * SM_STRIDE + k8 + tig];
                const float* p1 = p0 + 8 * SM_STRIDE;
                af[mi][0] = __float_as_uint(p0[0]);
                af[mi][1] = __float_as_uint(p1[0]);
                af[mi][2] = __float_as_uint(p0[4]);
                af[mi][3] = __float_as_uint(p1[4]);
            }
            #pragma unroll
            for (int ni = 0; ni < 4; ni++) {
                const float* p = &Bsb[(warpN + ni * 8 + grp) * SM_STRIDE + k8 + tig];
                bf[ni][0] = __float_as_uint(p[0]);
                bf[ni][1] = __float_as_uint(p[4]);
            }
            #pragma unroll
            for (int mi = 0; mi < 4; mi++)
                #pragma unroll
                for (int ni = 0; ni < 4; ni++) {
                    asm volatile(
                        "mma.sync.aligned.m16n8k8.row.col.f32.tf32.tf32.f32 "
                        "{%0,%1,%2,%3}, {%4,%5,%6,%7}, {%8,%9}, {%0,%1,%2,%3};"
                        : "+f"(acc[mi][ni][0]), "+f"(acc[mi][ni][1]),
                          "+f"(acc[mi][ni][2]), "+f"(acc[mi][ni][3])
                        : "r"(af[mi][0]), "r"(af[mi][1]), "r"(af[mi][2]), "r"(af[mi][3]),
                          "r"(bf[ni][0]), "r"(bf[ni][1]));
                }
        }
        if (c + 1 < nch) {
            int nb = (c + 1) & 1;
            #pragma unroll
            for (int t = 0; t < 4; t++) {
                float* pa = &As[nb * SM_TILE + (ldr + t * 32) * SM_STRIDE + ldc];
                pa[0] = __uint_as_float(f2tf32(sa[t].x));
                pa[1] = __uint_as_float(f2tf32(sa[t].y));
                pa[2] = __uint_as_float(f2tf32(sa[t].z));
                pa[3] = __uint_as_float(f2tf32(sa[t].w));
                *(float4*)&Bs[nb * SM_TILE + (ldr + t * 32) * SM_STRIDE + ldc] = sb[t];
            }
            __syncthreads();
        }
    }

    // epilogue: direct stores (float2 per fragment row-pair)
    #pragma unroll
    for (int mi = 0; mi < 4; mi++) {
        #pragma unroll
        for (int half = 0; half < 2; half++) {
            size_t r = (size_t)bm * 128 + warpM + mi * 16 + grp + half * 8;
            #pragma unroll
            for (int ni = 0; ni < 4; ni++) {
                int cg = bn * 128 + warpN + ni * 8 + tig * 2;
                float v0 = acc[mi][ni][half * 2 + 0];
                float v1 = acc[mi][ni][half * 2 + 1];
                if (BIAS) { v0 += bias[cg]; v1 += bias[cg + 1]; }
                if (GELU_ACT) {
                    v0 = 0.5f * v0 * (1.0f + erff(v0 * 0.70710678118654752f));
                    v1 = 0.5f * v1 * (1.0f + erff(v1 * 0.70710678118654752f));
                }
                size_t idx = r * (size_t)N + cg;
                if (RES) {
                    float2 r2 = *(const float2*)(res + idx);
                    v0 += r2.x; v1 += r2.y;
                }
                float2 o2; o2.x = v0; o2.y = v1;
                *(float2*)(C + idx) = o2;
            }
        }
    }
}

// ---------------- causal flash attention (fp32 SIMT, qkv packed stride 3072) ----------------
__global__ void __launch_bounds__(256) attn_kernel(
    const float* __restrict__ qkv, float* __restrict__ o)
{
    __shared__ float Qs [64 * 64];
    __shared__ float KPs[64 * 64];
    __shared__ float Vs [64 * 64];
    int qb = blockIdx.x, h = blockIdx.y, b = blockIdx.z;
    int tid = threadIdx.x;
    int tx = tid & 15, ty = tid >> 4;
    size_t base  = (size_t)b * T_SEQ * QKV_N + h * DH;
    size_t baseo = (size_t)b * T_SEQ * D_MODEL + h * DH;
    const float* q = qkv;
    const float* k = qkv + D_MODEL;
    const float* v = qkv + 2 * D_MODEL;

    for (int f = tid; f < 64 * 16; f += 256) {
        int r = f >> 4, d0 = (f & 15) << 2;
        float4 val = *(const float4*)(q + base + (size_t)(qb * 64 + r) * QKV_N + d0);
        Qs[r * 64 + d0 + 0] = val.x * 0.125f;
        Qs[r * 64 + d0 + 1] = val.y * 0.125f;
        Qs[r * 64 + d0 + 2] = val.z * 0.125f;
        Qs[r * 64 + d0 + 3] = val.w * 0.125f;
    }

    float m_[4], l_[4], oacc[4][4];
    #pragma unroll
    for (int i = 0; i < 4; i++) {
        m_[i] = -1e30f; l_[i] = 0.f;
        #pragma unroll
        for (int j = 0; j < 4; j++) oacc[i][j] = 0.f;
    }

    for (int kb = 0; kb <= qb; kb++) {
        for (int f = tid; f < 64 * 16; f += 256) {
            int r = f >> 4, d0 = (f & 15) << 2;
            float4 kv = *(const float4*)(k + base + (size_t)(kb * 64 + r) * QKV_N + d0);
            KPs[(d0 + 0) * 64 + ((r + d0 + 0) & 63)] = kv.x;
            KPs[(d0 + 1) * 64 + ((r + d0 + 1) & 63)] = kv.y;
            KPs[(d0 + 2) * 64 + ((r + d0 + 2) & 63)] = kv.z;
            KPs[(d0 + 3) * 64 + ((r + d0 + 3) & 63)] = kv.w;
            float4 vv = *(const float4*)(v + base + (size_t)(kb * 64 + r) * QKV_N + d0);
            *(float4*)&Vs[r * 64 + d0] = vv;
        }
        __syncthreads();

        float s[4][4];
        #pragma unroll
        for (int i = 0; i < 4; i++)
            #pragma unroll
            for (int j = 0; j < 4; j++) s[i][j] = 0.f;
        for (int d = 0; d < 64; d++) {
            float qr[4], kr[4];
            #pragma unroll
            for (int i = 0; i < 4; i++) qr[i] = Qs[(ty * 4 + i) * 64 + d];
            #pragma unroll
            for (int j = 0; j < 4; j++) kr[j] = KPs[d * 64 + ((tx * 4 + j + d) & 63)];
            #pragma unroll
            for (int i = 0; i < 4; i++)
                #pragma unroll
                for (int j = 0; j < 4; j++)
                    s[i][j] = fmaf(qr[i], kr[j], s[i][j]);
        }
        if (kb == qb) {
            #pragma unroll
            for (int i = 0; i < 4; i++)
                #pragma unroll
                for (int j = 0; j < 4; j++)
                    if (tx * 4 + j > ty * 4 + i) s[i][j] = -1e30f;
        }

        #pragma unroll
        for (int i = 0; i < 4; i++) {
            float rm = fmaxf(fmaxf(s[i][0], s[i][1]), fmaxf(s[i][2], s[i][3]));
            #pragma unroll
            for (int off = 8; off > 0; off >>= 1)
                rm = fmaxf(rm, __shfl_xor_sync(0xffffffffu, rm, off, 16));
            float mn = fmaxf(m_[i], rm);
            float alpha = __expf(m_[i] - mn);
            float rs = 0.f;
            #pragma unroll
            for (int j = 0; j < 4; j++) { s[i][j] = __expf(s[i][j] - mn); rs += s[i][j]; }
            #pragma unroll
            for (int off = 8; off > 0; off >>= 1)
                rs += __shfl_xor_sync(0xffffffffu, rs, off, 16);
            l_[i] = l_[i] * alpha + rs;
            m_[i] = mn;
            #pragma unroll
            for (int j = 0; j < 4; j++) oacc[i][j] *= alpha;
        }
        __syncthreads();

        #pragma unroll
        for (int i = 0; i < 4; i++)
            #pragma unroll
            for (int j = 0; j < 4; j++)
                KPs[(ty * 4 + i) * 64 + tx * 4 + j] = s[i][j];
        __syncthreads();

        for (int kk = 0; kk < 64; kk++) {
            float p[4], vv[4];
            #pragma unroll
            for (int i = 0; i < 4; i++) p[i] = KPs[(ty * 4 + i) * 64 + kk];
            #pragma unroll
            for (int j = 0; j < 4; j++) vv[j] = Vs[kk * 64 + tx * 4 + j];
            #pragma unroll
            for (int i = 0; i < 4; i++)
                #pragma unroll
                for (int j = 0; j < 4; j++)
                    oacc[i][j] = fmaf(p[i], vv[j], oacc[i][j]);
        }
        __syncthreads();
    }

    #pragma unroll
    for (int i = 0; i < 4; i++) {
        float invl = 1.f / l_[i];
        size_t rowbase = baseo + (size_t)(qb * 64 + ty * 4 + i) * D_MODEL + tx * 4;
        #pragma unroll
        for (int j = 0; j < 4; j++)
            o[rowbase + j] = oacc[i][j] * invl;
    }
}

// ---------------- launch ----------------
extern "C" void kernel_launch(void* const* d_in, const int* in_sizes, int n_in,
                              void* d_out, int out_size)
{
    const float* x  = (const float*)d_in[0];
    const float* Wq = (const float*)d_in[1];
    const float* Wk = (const float*)d_in[2];
    const float* Wv = (const float*)d_in[3];
    const float* Wo = (const float*)d_in[4];
    const float* W1 = (const float*)d_in[5];
    const float* b1 = (const float*)d_in[6];
    const float* W2 = (const float*)d_in[7];
    const float* b2 = (const float*)d_in[8];
    const float* g1 = (const float*)d_in[9];
    const float* g2 = (const float*)d_in[10];
    float* out = (float*)d_out;

    float *xn, *qkv, *attn, *x2, *hn, *f1, *wqkvT, *woT, *w1T, *w2T;
    cudaGetSymbolAddress((void**)&xn,    g_xn);
    cudaGetSymbolAddress((void**)&qkv,   g_qkv);
    cudaGetSymbolAddress((void**)&attn,  g_attn);
    cudaGetSymbolAddress((void**)&x2,    g_x2);
    cudaGetSymbolAddress((void**)&hn,    g_h);
    cudaGetSymbolAddress((void**)&f1,    g_f1);
    cudaGetSymbolAddress((void**)&wqkvT, g_wqkvT);
    cudaGetSymbolAddress((void**)&woT,   g_woT);
    cudaGetSymbolAddress((void**)&w1T,   g_w1T);
    cudaGetSymbolAddress((void**)&w2T,   g_w2T);

    const int SMEM_SZ = 4 * SM_TILE * sizeof(float);   // 73,728 B
    cudaFuncSetAttribute(gemm_mma<false, false, false>,
                         cudaFuncAttributeMaxDynamicSharedMemorySize, SMEM_SZ);
    cudaFuncSetAttribute(gemm_mma<false, false, true>,
                         cudaFuncAttributeMaxDynamicSharedMemorySize, SMEM_SZ);
    cudaFuncSetAttribute(gemm_mma<true, true, false>,
                         cudaFuncAttributeMaxDynamicSharedMemorySize, SMEM_SZ);
    cudaFuncSetAttribute(gemm_mma<true, false, true>,
                         cudaFuncAttributeMaxDynamicSharedMemorySize, SMEM_SZ);

    // weight transposes (tf32-rounded): W[K][N] -> WT[N][K]
    transpose_round<<<dim3(32, 32), 256>>>(Wq, wqkvT,                  D_MODEL, D_MODEL);
    transpose_round<<<dim3(32, 32), 256>>>(Wk, wqkvT + 1024 * D_MODEL, D_MODEL, D_MODEL);
    transpose_round<<<dim3(32, 32), 256>>>(Wv, wqkvT + 2048 * D_MODEL, D_MODEL, D_MODEL);
    transpose_round<<<dim3(32, 32), 256>>>(Wo, woT,                    D_MODEL, D_MODEL);
    transpose_round<<<dim3(128, 32), 256>>>(W1, w1T,                   D_MODEL, D_FF);
    transpose_round<<<dim3(32, 128), 256>>>(W2, w2T,                   D_FF,    D_MODEL);

    // x1 = rmsnorm(x, g1)
    rmsnorm_kernel<<<NTOK, 256>>>(x, g1, xn);
    // qkv = x1 @ [Wq|Wk|Wv]
    gemm_mma<false, false, false><<<dim3(QKV_N / 128, NTOK / 128), 256, SMEM_SZ>>>(
        xn, wqkvT, nullptr, nullptr, qkv, NTOK, QKV_N, D_MODEL);
    // causal attention
    attn_kernel<<<dim3(T_SEQ / 64, NH, BATCH), 256>>>(qkv, attn);
    // x2 = x + attn @ Wo
    gemm_mma<false, false, true><<<dim3(D_MODEL / 128, NTOK / 128), 256, SMEM_SZ>>>(
        attn, woT, nullptr, x, x2, NTOK, D_MODEL, D_MODEL);
    // h = rmsnorm(x2, g2)
    rmsnorm_kernel<<<NTOK, 256>>>(x2, g2, hn);
    // f1 = gelu(h @ W1 + b1)
    gemm_mma<true, true, false><<<dim3(D_FF / 128, NTOK / 128), 256, SMEM_SZ>>>(
        hn, w1T, b1, nullptr, f1, NTOK, D_FF, D_MODEL);
    // out = x2 + f1 @ W2 + b2
    gemm_mma<true, false, true><<<dim3(D_MODEL / 128, NTOK / 128), 256, SMEM_SZ>>>(
        f1, w2T, b2, x2, out, NTOK, D_MODEL, D_FF);
}

// round 4
// speedup vs baseline: 3.4017x; 1.7533x over previous
#include <cuda_runtime.h>
#include <math.h>
#include <cstdint>

#define D_MODEL 1024
#define T_SEQ   2048
#define BATCH   2
#define NTOK    (BATCH * T_SEQ)   // 4096
#define D_FF    4096
#define NH      16
#define DH      64
#define QKV_N   3072

// ---------------- scratch (no allocations allowed) ----------------
__device__ float g_xn   [NTOK * D_MODEL];
__device__ float g_qkv  [NTOK * QKV_N];
__device__ float g_attn [NTOK * D_MODEL];
__device__ float g_x2   [NTOK * D_MODEL];
__device__ float g_h    [NTOK * D_MODEL];
__device__ float g_f1   [NTOK * D_FF];
__device__ float g_wqkvT[QKV_N * D_MODEL];
__device__ float g_woT  [D_MODEL * D_MODEL];
__device__ float g_w1T  [D_FF * D_MODEL];
__device__ float g_w2T  [D_MODEL * D_FF];

__device__ __forceinline__ uint32_t f2tf32(float x) {
    uint32_t r; asm("cvt.rna.tf32.f32 %0, %1;" : "=r"(r) : "f"(x)); return r;
}
__device__ __forceinline__ uint32_t smem_u32(const void* p) {
    uint32_t a;
    asm("{ .reg .u64 t; cvta.to.shared.u64 t, %1; cvt.u32.u64 %0, t; }" : "=r"(a) : "l"(p));
    return a;
}
#define CP_ASYNC16(dst, src) \
    asm volatile("cp.async.cg.shared.global [%0], [%1], 16;" :: "r"(dst), "l"(src))
#define CP_COMMIT() asm volatile("cp.async.commit_group;")
#define CP_WAIT0()  asm volatile("cp.async.wait_group 0;")

#define MMA_TF32(c0, c1, c2, c3, a0, a1, a2, a3, b0, b1) \
    asm volatile( \
        "mma.sync.aligned.m16n8k8.row.col.f32.tf32.tf32.f32 " \
        "{%0,%1,%2,%3}, {%4,%5,%6,%7}, {%8,%9}, {%0,%1,%2,%3};" \
        : "+f"(c0), "+f"(c1), "+f"(c2), "+f"(c3) \
        : "r"(a0), "r"(a1), "r"(a2), "r"(a3), "r"(b0), "r"(b1))

// ---------------- weight transpose + tf32 round: W[K][N] -> WT[N][K] ----------------
__global__ void __launch_bounds__(256) transpose_round(
    const float* __restrict__ W, float* __restrict__ WT, int K, int N)
{
    __shared__ float t[32][33];
    int n0 = blockIdx.x * 32, k0 = blockIdx.y * 32;
    int tx = threadIdx.x & 31, ty = threadIdx.x >> 5;   // 32x8
    #pragma unroll
    for (int i = 0; i < 32; i += 8)
        t[ty + i][tx] = W[(size_t)(k0 + ty + i) * N + n0 + tx];
    __syncthreads();
    #pragma unroll
    for (int i = 0; i < 32; i += 8)
        WT[(size_t)(n0 + ty + i) * K + k0 + tx] = __uint_as_float(f2tf32(t[tx][ty + i]));
}

// ---------------- RMSNorm ----------------
__global__ void __launch_bounds__(256) rmsnorm_kernel(
    const float* __restrict__ x, const float* __restrict__ g, float* __restrict__ y)
{
    int row = blockIdx.x;
    int tid = threadIdx.x;
    const float4* xr = (const float4*)(x + (size_t)row * D_MODEL);
    float4 v = xr[tid];
    float s = v.x * v.x + v.y * v.y + v.z * v.z + v.w * v.w;
    #pragma unroll
    for (int o = 16; o > 0; o >>= 1) s += __shfl_xor_sync(0xffffffffu, s, o);
    __shared__ float red[8];
    if ((tid & 31) == 0) red[tid >> 5] = s;
    __syncthreads();
    float tot = red[0] + red[1] + red[2] + red[3] + red[4] + red[5] + red[6] + red[7];
    float inv = rsqrtf(tot * (1.0f / D_MODEL) + 1e-6f);
    float4 gv = ((const float4*)g)[tid];
    float4 o4;
    o4.x = v.x * inv * gv.x; o4.y = v.y * inv * gv.y;
    o4.z = v.z * inv * gv.z; o4.w = v.w * inv * gv.w;
    ((float4*)(y + (size_t)row * D_MODEL))[tid] = o4;
}

// ---------------- tf32 mma GEMM, cp.async double buffer ----------------
// Block tile 128x128, 8 warps (2M x 4N), warp tile 64x32 = 4x4 m16n8k8.
#define SM_STRIDE 36
#define SM_TILE   (128 * SM_STRIDE)

template<bool BIAS, bool GELU_ACT, bool RES>
__global__ void __launch_bounds__(256) gemm_mma(
    const float* __restrict__ A, const float* __restrict__ BT,
    const float* __restrict__ bias, const float* __restrict__ res,
    float* __restrict__ C, int M, int N, int K)
{
    extern __shared__ float sm[];
    float* As = sm;
    float* Bs = sm + 2 * SM_TILE;

    int tid = threadIdx.x;
    int lane = tid & 31, wid = tid >> 5;
    int warpM = (wid & 1) * 64;
    int warpN = (wid >> 1) * 32;
    int grp = lane >> 2, tig = lane & 3;
    int bn = blockIdx.x, bm = blockIdx.y;

    const float* Ab = A  + (size_t)bm * 128 * K;
    const float* Bb = BT + (size_t)bn * 128 * K;

    int ldr = tid >> 3;                // 0..31
    int ldc = (tid & 7) << 2;          // 0..28
    const float* Aptr = Ab + (size_t)ldr * K + ldc;
    const float* Bptr = Bb + (size_t)ldr * K + ldc;
    uint32_t dA = smem_u32(As) + (uint32_t)(ldr * SM_STRIDE + ldc) * 4;
    uint32_t dB = smem_u32(Bs) + (uint32_t)(ldr * SM_STRIDE + ldc) * 4;

    float acc[4][4][4];
    #pragma unroll
    for (int mi = 0; mi < 4; mi++)
        #pragma unroll
        for (int ni = 0; ni < 4; ni++)
            #pragma unroll
            for (int r = 0; r < 4; r++) acc[mi][ni][r] = 0.f;

    int nch = K >> 5;

    // prologue: chunk 0
    #pragma unroll
    for (int t = 0; t < 4; t++) {
        CP_ASYNC16(dA + (uint32_t)(t * 32 * SM_STRIDE) * 4, Aptr + (size_t)t * 32 * K);
        CP_ASYNC16(dB + (uint32_t)(t * 32 * SM_STRIDE) * 4, Bptr + (size_t)t * 32 * K);
    }
    CP_COMMIT();

    for (int c = 0; c < nch; c++) {
        CP_WAIT0();
        __syncthreads();
        if (c + 1 < nch) {
            int k0 = (c + 1) << 5;
            uint32_t boff = (uint32_t)(((c + 1) & 1) * SM_TILE) * 4;
            #pragma unroll
            for (int t = 0; t < 4; t++) {
                CP_ASYNC16(dA + boff + (uint32_t)(t * 32 * SM_STRIDE) * 4,
                           Aptr + (size_t)t * 32 * K + k0);
                CP_ASYNC16(dB + boff + (uint32_t)(t * 32 * SM_STRIDE) * 4,
                           Bptr + (size_t)t * 32 * K + k0);
            }
            CP_COMMIT();
        }
        const float* Asb = &As[(c & 1) * SM_TILE];
        const float* Bsb = &Bs[(c & 1) * SM_TILE];
        #pragma unroll
        for (int kk = 0; kk < 4; kk++) {
            int k8 = kk << 3;
            uint32_t af[4][4], bf[4][2];
            #pragma unroll
            for (int mi = 0; mi < 4; mi++) {
                const float* p0 = &Asb[(warpM + mi * 16 + grp) * SM_STRIDE + k8 + tig];
                const float* p1 = p0 + 8 * SM_STRIDE;
                af[mi][0] = __float_as_uint(p0[0]);
                af[mi][1] = __float_as_uint(p1[0]);
                af[mi][2] = __float_as_uint(p0[4]);
                af[mi][3] = __float_as_uint(p1[4]);
            }
            #pragma unroll
            for (int ni = 0; ni < 4; ni++) {
                const float* p = &Bsb[(warpN + ni * 8 + grp) * SM_STRIDE + k8 + tig];
                bf[ni][0] = __float_as_uint(p[0]);
                bf[ni][1] = __float_as_uint(p[4]);
            }
            #pragma unroll
            for (int mi = 0; mi < 4; mi++)
                #pragma unroll
                for (int ni = 0; ni < 4; ni++)
                    MMA_TF32(acc[mi][ni][0], acc[mi][ni][1], acc[mi][ni][2], acc[mi][ni][3],
                             af[mi][0], af[mi][1], af[mi][2], af[mi][3],
                             bf[ni][0], bf[ni][1]);
        }
        __syncthreads();
    }

    #pragma unroll
    for (int mi = 0; mi < 4; mi++) {
        #pragma unroll
        for (int half = 0; half < 2; half++) {
            size_t r = (size_t)bm * 128 + warpM + mi * 16 + grp + half * 8;
            #pragma unroll
            for (int ni = 0; ni < 4; ni++) {
                int cg = bn * 128 + warpN + ni * 8 + tig * 2;
                float v0 = acc[mi][ni][half * 2 + 0];
                float v1 = acc[mi][ni][half * 2 + 1];
                if (BIAS) { v0 += bias[cg]; v1 += bias[cg + 1]; }
                if (GELU_ACT) {
                    v0 = 0.5f * v0 * (1.0f + erff(v0 * 0.70710678118654752f));
                    v1 = 0.5f * v1 * (1.0f + erff(v1 * 0.70710678118654752f));
                }
                size_t idx = r * (size_t)N + cg;
                if (RES) {
                    float2 r2 = *(const float2*)(res + idx);
                    v0 += r2.x; v1 += r2.y;
                }
                float2 o2; o2.x = v0; o2.y = v1;
                *(float2*)(C + idx) = o2;
            }
        }
    }
}

// ---------------- tf32 mma causal flash attention ----------------
// 64 q-rows per CTA, 4 warps x 16 rows. K/V tiles 64x64 natural layout.
// Strides: Qs/Ks/Ps 68 (conflict-free a/b frag reads), Vs 72.
#define QS_STR 68
#define KS_STR 68
#define VS_STR 72
#define PS_STR 68
#define ATTN_SMEM ((64 * QS_STR + 64 * KS_STR + 64 * VS_STR + 4 * 16 * PS_STR) * 4)

__global__ void __launch_bounds__(128) attn_mma(
    const float* __restrict__ qkv, float* __restrict__ o)
{
    extern __shared__ float smf[];
    float* Qs = smf;
    float* Ks = Qs + 64 * QS_STR;
    float* Vs = Ks + 64 * KS_STR;
    int tid = threadIdx.x;
    int lane = tid & 31, wid = tid >> 5;
    int grp = lane >> 2, tig = lane & 3;
    float* Ps = Vs + 64 * VS_STR + wid * 16 * PS_STR;

    int qb = gridDim.x - 1 - blockIdx.x;   // heavy tiles first
    int h = blockIdx.y, b = blockIdx.z;
    size_t base  = (size_t)b * T_SEQ * QKV_N + h * DH;
    size_t baseo = (size_t)b * T_SEQ * D_MODEL + h * DH;
    const float* qg = qkv + base;
    const float* kg = qkv + base + D_MODEL;
    const float* vg = qkv + base + 2 * D_MODEL;

    // load Q (scaled by 1/sqrt(Dh)=0.125)
    for (int f = tid; f < 64 * 16; f += 128) {
        int r = f >> 4, c4 = (f & 15) << 2;
        float4 v = *(const float4*)(qg + (size_t)(qb * 64 + r) * QKV_N + c4);
        float* p = &Qs[r * QS_STR + c4];
        p[0] = v.x * 0.125f; p[1] = v.y * 0.125f;
        p[2] = v.z * 0.125f; p[3] = v.w * 0.125f;
    }

    float m0 = -1e30f, m1 = -1e30f, l0 = 0.f, l1 = 0.f;
    float oa[8][4];
    #pragma unroll
    for (int ni = 0; ni < 8; ni++)
        #pragma unroll
        for (int r = 0; r < 4; r++) oa[ni][r] = 0.f;

    int row_l0 = wid * 16 + grp;       // local q row (0..63)
    int row_l1 = row_l0 + 8;

    for (int kb = 0; kb <= qb; kb++) {
        __syncthreads();
        for (int f = tid; f < 64 * 16; f += 128) {
            int r = f >> 4, c4 = (f & 15) << 2;
            float4 kv = *(const float4*)(kg + (size_t)(kb * 64 + r) * QKV_N + c4);
            *(float4*)&Ks[r * KS_STR + c4] = kv;
            float4 vv = *(const float4*)(vg + (size_t)(kb * 64 + r) * QKV_N + c4);
            *(float4*)&Vs[r * VS_STR + c4] = vv;
        }
        __syncthreads();

        // S = Q @ K^T
        float s[8][4];
        #pragma unroll
        for (int ni = 0; ni < 8; ni++)
            #pragma unroll
            for (int r = 0; r < 4; r++) s[ni][r] = 0.f;
        #pragma unroll
        for (int ks = 0; ks < 8; ks++) {
            int k8 = ks << 3;
            const float* qp = &Qs[row_l0 * QS_STR + k8 + tig];
            uint32_t a0 = __float_as_uint(qp[0]);
            uint32_t a1 = __float_as_uint(qp[8 * QS_STR]);
            uint32_t a2 = __float_as_uint(qp[4]);
            uint32_t a3 = __float_as_uint(qp[8 * QS_STR + 4]);
            #pragma unroll
            for (int ni = 0; ni < 8; ni++) {
                const float* kp = &Ks[(ni * 8 + grp) * KS_STR + k8 + tig];
                uint32_t b0 = __float_as_uint(kp[0]);
                uint32_t b1 = __float_as_uint(kp[4]);
                MMA_TF32(s[ni][0], s[ni][1], s[ni][2], s[ni][3], a0, a1, a2, a3, b0, b1);
            }
        }
        if (kb == qb) {
            #pragma unroll
            for (int ni = 0; ni < 8; ni++) {
                int c0 = ni * 8 + tig * 2, c1 = c0 + 1;
                if (c0 > row_l0) s[ni][0] = -1e30f;
                if (c1 > row_l0) s[ni][1] = -1e30f;
                if (c0 > row_l1) s[ni][2] = -1e30f;
                if (c1 > row_l1) s[ni][3] = -1e30f;
            }
        }

        // online softmax (rows grp / grp+8, reduce over 16 cols + quad shfl)
        float rm0 = -1e30f, rm1 = -1e30f;
        #pragma unroll
        for (int ni = 0; ni < 8; ni++) {
            rm0 = fmaxf(rm0, fmaxf(s[ni][0], s[ni][1]));
            rm1 = fmaxf(rm1, fmaxf(s[ni][2], s[ni][3]));
        }
        rm0 = fmaxf(rm0, __shfl_xor_sync(0xffffffffu, rm0, 1));
        rm0 = fmaxf(rm0, __shfl_xor_sync(0xffffffffu, rm0, 2));
        rm1 = fmaxf(rm1, __shfl_xor_sync(0xffffffffu, rm1, 1));
        rm1 = fmaxf(rm1, __shfl_xor_sync(0xffffffffu, rm1, 2));
        float mn0 = fmaxf(m0, rm0), mn1 = fmaxf(m1, rm1);
        float al0 = __expf(m0 - mn0), al1 = __expf(m1 - mn1);
        float rs0 = 0.f, rs1 = 0.f;
        #pragma unroll
        for (int ni = 0; ni < 8; ni++) {
            s[ni][0] = __expf(s[ni][0] - mn0); rs0 += s[ni][0];
            s[ni][1] = __expf(s[ni][1] - mn0); rs0 += s[ni][1];
            s[ni][2] = __expf(s[ni][2] - mn1); rs1 += s[ni][2];
            s[ni][3] = __expf(s[ni][3] - mn1); rs1 += s[ni][3];
        }
        rs0 += __shfl_xor_sync(0xffffffffu, rs0, 1);
        rs0 += __shfl_xor_sync(0xffffffffu, rs0, 2);
        rs1 += __shfl_xor_sync(0xffffffffu, rs1, 1);
        rs1 += __shfl_xor_sync(0xffffffffu, rs1, 2);
        l0 = l0 * al0 + rs0; l1 = l1 * al1 + rs1;
        m0 = mn0; m1 = mn1;
        #pragma unroll
        for (int ni = 0; ni < 8; ni++) {
            oa[ni][0] *= al0; oa[ni][1] *= al0;
            oa[ni][2] *= al1; oa[ni][3] *= al1;
        }

        // P -> per-warp smem
        #pragma unroll
        for (int ni = 0; ni < 8; ni++) {
            int cc = ni * 8 + tig * 2;
            *(float2*)&Ps[grp * PS_STR + cc]       = make_float2(s[ni][0], s[ni][1]);
            *(float2*)&Ps[(grp + 8) * PS_STR + cc] = make_float2(s[ni][2], s[ni][3]);
        }
        __syncwarp();

        // O += P @ V
        #pragma unroll
        for (int ks = 0; ks < 8; ks++) {
            int k8 = ks << 3;
            const float* pp = &Ps[grp * PS_STR + k8 + tig];
            uint32_t a0 = __float_as_uint(pp[0]);
            uint32_t a1 = __float_as_uint(pp[8 * PS_STR]);
            uint32_t a2 = __float_as_uint(pp[4]);
            uint32_t a3 = __float_as_uint(pp[8 * PS_STR + 4]);
            #pragma unroll
            for (int ni = 0; ni < 8; ni++) {
                const float* vp = &Vs[(k8 + tig) * VS_STR + ni * 8 + grp];
                uint32_t b0 = __float_as_uint(vp[0]);
                uint32_t b1 = __float_as_uint(vp[4 * VS_STR]);
                MMA_TF32(oa[ni][0], oa[ni][1], oa[ni][2], oa[ni][3], a0, a1, a2, a3, b0, b1);
            }
        }
        __syncwarp();
    }

    float inv0 = 1.f / l0, inv1 = 1.f / l1;
    size_t r0 = baseo + (size_t)(qb * 64 + row_l0) * D_MODEL;
    size_t r1 = baseo + (size_t)(qb * 64 + row_l1) * D_MODEL;
    #pragma unroll
    for (int ni = 0; ni < 8; ni++) {
        int cc = ni * 8 + tig * 2;
        *(float2*)(o + r0 + cc) = make_float2(oa[ni][0] * inv0, oa[ni][1] * inv0);
        *(float2*)(o + r1 + cc) = make_float2(oa[ni][2] * inv1, oa[ni][3] * inv1);
    }
}

// ---------------- launch ----------------
extern "C" void kernel_launch(void* const* d_in, const int* in_sizes, int n_in,
                              void* d_out, int out_size)
{
    const float* x  = (const float*)d_in[0];
    const float* Wq = (const float*)d_in[1];
    const float* Wk = (const float*)d_in[2];
    const float* Wv = (const float*)d_in[3];
    const float* Wo = (const float*)d_in[4];
    const float* W1 = (const float*)d_in[5];
    const float* b1 = (const float*)d_in[6];
    const float* W2 = (const float*)d_in[7];
    const float* b2 = (const float*)d_in[8];
    const float* g1 = (const float*)d_in[9];
    const float* g2 = (const float*)d_in[10];
    float* out = (float*)d_out;

    float *xn, *qkv, *attn, *x2, *hn, *f1, *wqkvT, *woT, *w1T, *w2T;
    cudaGetSymbolAddress((void**)&xn,    g_xn);
    cudaGetSymbolAddress((void**)&qkv,   g_qkv);
    cudaGetSymbolAddress((void**)&attn,  g_attn);
    cudaGetSymbolAddress((void**)&x2,    g_x2);
    cudaGetSymbolAddress((void**)&hn,    g_h);
    cudaGetSymbolAddress((void**)&f1,    g_f1);
    cudaGetSymbolAddress((void**)&wqkvT, g_wqkvT);
    cudaGetSymbolAddress((void**)&woT,   g_woT);
    cudaGetSymbolAddress((void**)&w1T,   g_w1T);
    cudaGetSymbolAddress((void**)&w2T,   g_w2T);

    const int SMEM_SZ = 4 * SM_TILE * sizeof(float);   // 73,728 B
    cudaFuncSetAttribute(gemm_mma<false, false, false>,
                         cudaFuncAttributeMaxDynamicSharedMemorySize, SMEM_SZ);
    cudaFuncSetAttribute(gemm_mma<false, false, true>,
                         cudaFuncAttributeMaxDynamicSharedMemorySize, SMEM_SZ);
    cudaFuncSetAttribute(gemm_mma<true, true, false>,
                         cudaFuncAttributeMaxDynamicSharedMemorySize, SMEM_SZ);
    cudaFuncSetAttribute(gemm_mma<true, false, true>,
                         cudaFuncAttributeMaxDynamicSharedMemorySize, SMEM_SZ);
    cudaFuncSetAttribute(attn_mma,
                         cudaFuncAttributeMaxDynamicSharedMemorySize, ATTN_SMEM);

    // weight transposes (tf32-rounded): W[K][N] -> WT[N][K]
    transpose_round<<<dim3(32, 32), 256>>>(Wq, wqkvT,                  D_MODEL, D_MODEL);
    transpose_round<<<dim3(32, 32), 256>>>(Wk, wqkvT + 1024 * D_MODEL, D_MODEL, D_MODEL);
    transpose_round<<<dim3(32, 32), 256>>>(Wv, wqkvT + 2048 * D_MODEL, D_MODEL, D_MODEL);
    transpose_round<<<dim3(32, 32), 256>>>(Wo, woT,                    D_MODEL, D_MODEL);
    transpose_round<<<dim3(128, 32), 256>>>(W1, w1T,                   D_MODEL, D_FF);
    transpose_round<<<dim3(32, 128), 256>>>(W2, w2T,                   D_FF,    D_MODEL);

    rmsnorm_kernel<<<NTOK, 256>>>(x, g1, xn);
    gemm_mma<false, false, false><<<dim3(QKV_N / 128, NTOK / 128), 256, SMEM_SZ>>>(
        xn, wqkvT, nullptr, nullptr, qkv, NTOK, QKV_N, D_MODEL);
    attn_mma<<<dim3(T_SEQ / 64, NH, BATCH), 128, ATTN_SMEM>>>(qkv, attn);
    gemm_mma<false, false, true><<<dim3(D_MODEL / 128, NTOK / 128), 256, SMEM_SZ>>>(
        attn, woT, nullptr, x, x2, NTOK, D_MODEL, D_MODEL);
    rmsnorm_kernel<<<NTOK, 256>>>(x2, g2, hn);
    gemm_mma<true, true, false><<<dim3(D_FF / 128, NTOK / 128), 256, SMEM_SZ>>>(
        hn, w1T, b1, nullptr, f1, NTOK, D_FF, D_MODEL);
    gemm_mma<true, false, true><<<dim3(D_MODEL / 128, NTOK / 128), 256, SMEM_SZ>>>(
        f1, w2T, b2, x2, out, NTOK, D_MODEL, D_FF);
}

// round 5
// speedup vs baseline: 3.5257x; 1.0364x over previous
#include <cuda_runtime.h>
#include <math.h>
#include <cstdint>

#define D_MODEL 1024
#define T_SEQ   2048
#define BATCH   2
#define NTOK    (BATCH * T_SEQ)   // 4096
#define D_FF    4096
#define NH      16
#define DH      64
#define QKV_N   3072

// ---------------- scratch (no allocations allowed) ----------------
__device__ float g_xn   [NTOK * D_MODEL];
__device__ float g_qkv  [NTOK * QKV_N];
__device__ float g_attn [NTOK * D_MODEL];
__device__ float g_x2   [NTOK * D_MODEL];
__device__ float g_h    [NTOK * D_MODEL];
__device__ float g_f1   [NTOK * D_FF];
__device__ float g_wqkvT[QKV_N * D_MODEL];
__device__ float g_woT  [D_MODEL * D_MODEL];
__device__ float g_w1T  [D_FF * D_MODEL];
__device__ float g_w2T  [D_MODEL * D_FF];

__device__ __forceinline__ uint32_t f2tf32(float x) {
    uint32_t r; asm("cvt.rna.tf32.f32 %0, %1;" : "=r"(r) : "f"(x)); return r;
}
__device__ __forceinline__ uint32_t smem_u32(const void* p) {
    uint32_t a;
    asm("{ .reg .u64 t; cvta.to.shared.u64 t, %1; cvt.u32.u64 %0, t; }" : "=r"(a) : "l"(p));
    return a;
}
#define CP_ASYNC16(dst, src) \
    asm volatile("cp.async.cg.shared.global [%0], [%1], 16;" :: "r"(dst), "l"(src))
#define CP_COMMIT() asm volatile("cp.async.commit_group;")
#define CP_WAIT0()  asm volatile("cp.async.wait_group 0;")

#define MMA_TF32(c0, c1, c2, c3, a0, a1, a2, a3, b0, b1) \
    asm volatile( \
        "mma.sync.aligned.m16n8k8.row.col.f32.tf32.tf32.f32 " \
        "{%0,%1,%2,%3}, {%4,%5,%6,%7}, {%8,%9}, {%0,%1,%2,%3};" \
        : "+f"(c0), "+f"(c1), "+f"(c2), "+f"(c3) \
        : "r"(a0), "r"(a1), "r"(a2), "r"(a3), "r"(b0), "r"(b1))

#define LDSM4(r0, r1, r2, r3, a) \
    asm volatile("ldmatrix.sync.aligned.m8n8.x4.shared.b16 {%0,%1,%2,%3}, [%4];" \
        : "=r"(r0), "=r"(r1), "=r"(r2), "=r"(r3) : "r"(a))

// ---------------- weight transpose + tf32 round: W[K][N] -> WT[N][K] ----------------
__global__ void __launch_bounds__(256) transpose_round(
    const float* __restrict__ W, float* __restrict__ WT, int K, int N)
{
    __shared__ float t[32][33];
    int n0 = blockIdx.x * 32, k0 = blockIdx.y * 32;
    int tx = threadIdx.x & 31, ty = threadIdx.x >> 5;   // 32x8
    #pragma unroll
    for (int i = 0; i < 32; i += 8)
        t[ty + i][tx] = W[(size_t)(k0 + ty + i) * N + n0 + tx];
    __syncthreads();
    #pragma unroll
    for (int i = 0; i < 32; i += 8)
        WT[(size_t)(n0 + ty + i) * K + k0 + tx] = __uint_as_float(f2tf32(t[tx][ty + i]));
}

// ---------------- RMSNorm ----------------
__global__ void __launch_bounds__(256) rmsnorm_kernel(
    const float* __restrict__ x, const float* __restrict__ g, float* __restrict__ y)
{
    int row = blockIdx.x;
    int tid = threadIdx.x;
    const float4* xr = (const float4*)(x + (size_t)row * D_MODEL);
    float4 v = xr[tid];
    float s = v.x * v.x + v.y * v.y + v.z * v.z + v.w * v.w;
    #pragma unroll
    for (int o = 16; o > 0; o >>= 1) s += __shfl_xor_sync(0xffffffffu, s, o);
    __shared__ float red[8];
    if ((tid & 31) == 0) red[tid >> 5] = s;
    __syncthreads();
    float tot = red[0] + red[1] + red[2] + red[3] + red[4] + red[5] + red[6] + red[7];
    float inv = rsqrtf(tot * (1.0f / D_MODEL) + 1e-6f);
    float4 gv = ((const float4*)g)[tid];
    float4 o4;
    o4.x = v.x * inv * gv.x; o4.y = v.y * inv * gv.y;
    o4.z = v.z * inv * gv.z; o4.w = v.w * inv * gv.w;
    ((float4*)(y + (size_t)row * D_MODEL))[tid] = o4;
}

// ---------------- tf32 mma GEMM: cp.async double buffer + ldmatrix frags ----------------
#define SM_STRIDE 36
#define SM_TILE   (128 * SM_STRIDE)

template<bool BIAS, bool GELU_ACT, bool RES>
__global__ void __launch_bounds__(256) gemm_mma(
    const float* __restrict__ A, const float* __restrict__ BT,
    const float* __restrict__ bias, const float* __restrict__ res,
    float* __restrict__ C, int M, int N, int K)
{
    extern __shared__ float sm[];
    float* As = sm;
    float* Bs = sm + 2 * SM_TILE;

    int tid = threadIdx.x;
    int lane = tid & 31, wid = tid >> 5;
    int warpM = (wid & 1) * 64;
    int warpN = (wid >> 1) * 32;
    int grp = lane >> 2, tig = lane & 3;
    int bn = blockIdx.x, bm = blockIdx.y;

    const float* Ab = A  + (size_t)bm * 128 * K;
    const float* Bb = BT + (size_t)bn * 128 * K;

    int ldr = tid >> 3;                // 0..31
    int ldc = (tid & 7) << 2;          // 0..28
    const float* Aptr = Ab + (size_t)ldr * K + ldc;
    const float* Bptr = Bb + (size_t)ldr * K + ldc;
    uint32_t AsU = smem_u32(As), BsU = smem_u32(Bs);
    uint32_t dA = AsU + (uint32_t)(ldr * SM_STRIDE + ldc) * 4;
    uint32_t dB = BsU + (uint32_t)(ldr * SM_STRIDE + ldc) * 4;

    // ldmatrix lane-addresses (m = lane>>3 selects 8x8 sub-matrix)
    int m8 = lane >> 3, l8 = lane & 7;
    // A: m0 rows+0 col0 | m1 rows+8 col0 | m2 rows+0 col+4 | m3 rows+8 col+4
    uint32_t aOff[4], bOff[2];
    {
        int ar = warpM + ((m8 & 1) << 3) + l8;
        int ac = (m8 >> 1) << 2;
        #pragma unroll
        for (int mi = 0; mi < 4; mi++)
            aOff[mi] = (uint32_t)((ar + mi * 16) * SM_STRIDE + ac) * 4;
        // B: m0 rows(ni0)+0 col0 | m1 rows(ni0)+0 col+4 | m2 rows+8 col0 | m3 rows+8 col+4
        int br = warpN + ((m8 >> 1) << 3) + l8;
        int bc = (m8 & 1) << 2;
        #pragma unroll
        for (int j = 0; j < 2; j++)
            bOff[j] = (uint32_t)((br + j * 16) * SM_STRIDE + bc) * 4;
    }

    float acc[4][4][4];
    #pragma unroll
    for (int mi = 0; mi < 4; mi++)
        #pragma unroll
        for (int ni = 0; ni < 4; ni++)
            #pragma unroll
            for (int r = 0; r < 4; r++) acc[mi][ni][r] = 0.f;

    int nch = K >> 5;

    #pragma unroll
    for (int t = 0; t < 4; t++) {
        CP_ASYNC16(dA + (uint32_t)(t * 32 * SM_STRIDE) * 4, Aptr + (size_t)t * 32 * K);
        CP_ASYNC16(dB + (uint32_t)(t * 32 * SM_STRIDE) * 4, Bptr + (size_t)t * 32 * K);
    }
    CP_COMMIT();

    for (int c = 0; c < nch; c++) {
        CP_WAIT0();
        __syncthreads();
        if (c + 1 < nch) {
            int k0 = (c + 1) << 5;
            uint32_t boff = (uint32_t)(((c + 1) & 1) * SM_TILE) * 4;
            #pragma unroll
            for (int t = 0; t < 4; t++) {
                CP_ASYNC16(dA + boff + (uint32_t)(t * 32 * SM_STRIDE) * 4,
                           Aptr + (size_t)t * 32 * K + k0);
                CP_ASYNC16(dB + boff + (uint32_t)(t * 32 * SM_STRIDE) * 4,
                           Bptr + (size_t)t * 32 * K + k0);
            }
            CP_COMMIT();
        }
        uint32_t abuf = AsU + (uint32_t)((c & 1) * SM_TILE) * 4;
        uint32_t bbuf = BsU + (uint32_t)((c & 1) * SM_TILE) * 4;
        uint32_t aRel = abuf - AsU, bRel = bbuf - BsU;
        #pragma unroll
        for (int kk = 0; kk < 4; kk++) {
            uint32_t kb = (uint32_t)kk * 32;
            uint32_t af[4][4], bf[4][2];
            #pragma unroll
            for (int mi = 0; mi < 4; mi++)
                LDSM4(af[mi][0], af[mi][1], af[mi][2], af[mi][3],
                      AsU + aRel + aOff[mi] + kb);
            #pragma unroll
            for (int j = 0; j < 2; j++)
                LDSM4(bf[2 * j][0], bf[2 * j][1], bf[2 * j + 1][0], bf[2 * j + 1][1],
                      BsU + bRel + bOff[j] + kb);
            #pragma unroll
            for (int mi = 0; mi < 4; mi++)
                #pragma unroll
                for (int ni = 0; ni < 4; ni++)
                    MMA_TF32(acc[mi][ni][0], acc[mi][ni][1], acc[mi][ni][2], acc[mi][ni][3],
                             af[mi][0], af[mi][1], af[mi][2], af[mi][3],
                             bf[ni][0], bf[ni][1]);
        }
        __syncthreads();
    }

    #pragma unroll
    for (int mi = 0; mi < 4; mi++) {
        #pragma unroll
        for (int half = 0; half < 2; half++) {
            size_t r = (size_t)bm * 128 + warpM + mi * 16 + grp + half * 8;
            #pragma unroll
            for (int ni = 0; ni < 4; ni++) {
                int cg = bn * 128 + warpN + ni * 8 + tig * 2;
                float v0 = acc[mi][ni][half * 2 + 0];
                float v1 = acc[mi][ni][half * 2 + 1];
                if (BIAS) { v0 += bias[cg]; v1 += bias[cg + 1]; }
                if (GELU_ACT) {
                    v0 = 0.5f * v0 * (1.0f + erff(v0 * 0.70710678118654752f));
                    v1 = 0.5f * v1 * (1.0f + erff(v1 * 0.70710678118654752f));
                }
                size_t idx = r * (size_t)N + cg;
                if (RES) {
                    float2 r2 = *(const float2*)(res + idx);
                    v0 += r2.x; v1 += r2.y;
                }
                float2 o2; o2.x = v0; o2.y = v1;
                *(float2*)(C + idx) = o2;
            }
        }
    }
}

// ---------------- tf32 mma causal flash attention ----------------
// 64 q-rows/CTA, 4 warps x 16 rows. cp.async double-buffered K/V, ldmatrix frags.
#define QS_STR 68
#define KS_STR 68
#define VS_STR 72
#define PS_STR 68
#define Q_FL   (64 * QS_STR)
#define K_FL   (64 * KS_STR)
#define V_FL   (64 * VS_STR)
#define P_FL   (16 * PS_STR)
#define ATTN_SMEM ((Q_FL + 2 * K_FL + 2 * V_FL + 4 * P_FL) * 4)

__global__ void __launch_bounds__(128) attn_mma(
    const float* __restrict__ qkv, float* __restrict__ o)
{
    extern __shared__ float smf[];
    float* Qs = smf;
    float* Ks = Qs + Q_FL;            // 2 buffers
    float* Vs = Ks + 2 * K_FL;        // 2 buffers
    int tid = threadIdx.x;
    int lane = tid & 31, wid = tid >> 5;
    int grp = lane >> 2, tig = lane & 3;
    float* Ps = Vs + 2 * V_FL + wid * P_FL;

    uint32_t QsU = smem_u32(Qs), KsU = smem_u32(Ks), VsU = smem_u32(Vs);
    uint32_t PsU = smem_u32(Ps);

    int qb = gridDim.x - 1 - blockIdx.x;   // heavy tiles first
    int h = blockIdx.y, b = blockIdx.z;
    size_t base  = (size_t)b * T_SEQ * QKV_N + h * DH;
    size_t baseo = (size_t)b * T_SEQ * D_MODEL + h * DH;
    const float* qg = qkv + base;
    const float* kg = qkv + base + D_MODEL;
    const float* vg = qkv + base + 2 * D_MODEL;

    // ldmatrix lane offsets
    int m8 = lane >> 3, l8 = lane & 7;
    uint32_t qOff = (uint32_t)(((wid * 16) + ((m8 & 1) << 3) + l8) * QS_STR
                               + (((m8 >> 1)) << 2)) * 4;
    uint32_t kOff[4];
    {
        int kr = ((m8 >> 1) << 3) + l8;
        int kc = (m8 & 1) << 2;
        #pragma unroll
        for (int j = 0; j < 4; j++)
            kOff[j] = (uint32_t)((kr + j * 16) * KS_STR + kc) * 4;
    }
    uint32_t pOff = (uint32_t)((((m8 & 1) << 3) + l8) * PS_STR + ((m8 >> 1) << 2)) * 4;

    // cp.async K/V loader coords
    int ldr = tid >> 4;                    // 0..7 (row step 8)
    int ldc = (tid & 15) << 2;             // 0..60

    // load Q (scaled by 1/sqrt(Dh)=0.125)
    for (int f = tid; f < 64 * 16; f += 128) {
        int r = f >> 4, c4 = (f & 15) << 2;
        float4 v = *(const float4*)(qg + (size_t)(qb * 64 + r) * QKV_N + c4);
        float* p = &Qs[r * QS_STR + c4];
        p[0] = v.x * 0.125f; p[1] = v.y * 0.125f;
        p[2] = v.z * 0.125f; p[3] = v.w * 0.125f;
    }

    // prologue: async load K/V tile 0 into buffer 0
    #pragma unroll
    for (int t = 0; t < 8; t++) {
        int r = ldr + t * 8;
        CP_ASYNC16(KsU + (uint32_t)(r * KS_STR + ldc) * 4,
                   kg + (size_t)r * QKV_N + ldc);
        CP_ASYNC16(VsU + (uint32_t)(r * VS_STR + ldc) * 4,
                   vg + (size_t)r * QKV_N + ldc);
    }
    CP_COMMIT();

    float m0 = -1e30f, m1 = -1e30f, l0 = 0.f, l1 = 0.f;
    float oa[8][4];
    #pragma unroll
    for (int ni = 0; ni < 8; ni++)
        #pragma unroll
        for (int r = 0; r < 4; r++) oa[ni][r] = 0.f;

    int row_l0 = wid * 16 + grp;
    int row_l1 = row_l0 + 8;

    for (int kb = 0; kb <= qb; kb++) {
        CP_WAIT0();
        __syncthreads();
        if (kb < qb) {
            uint32_t kbuf = KsU + (uint32_t)(((kb + 1) & 1) * K_FL) * 4;
            uint32_t vbuf = VsU + (uint32_t)(((kb + 1) & 1) * V_FL) * 4;
            const float* kgn = kg + (size_t)(kb + 1) * 64 * QKV_N;
            const float* vgn = vg + (size_t)(kb + 1) * 64 * QKV_N;
            #pragma unroll
            for (int t = 0; t < 8; t++) {
                int r = ldr + t * 8;
                CP_ASYNC16(kbuf + (uint32_t)(r * KS_STR + ldc) * 4,
                           kgn + (size_t)r * QKV_N + ldc);
                CP_ASYNC16(vbuf + (uint32_t)(r * VS_STR + ldc) * 4,
                           vgn + (size_t)r * QKV_N + ldc);
            }
            CP_COMMIT();
        }
        uint32_t kcur = KsU + (uint32_t)((kb & 1) * K_FL) * 4;
        const float* Vcur = Vs + (kb & 1) * V_FL;

        // S = Q @ K^T
        float s[8][4];
        #pragma unroll
        for (int ni = 0; ni < 8; ni++)
            #pragma unroll
            for (int r = 0; r < 4; r++) s[ni][r] = 0.f;
        #pragma unroll
        for (int ks = 0; ks < 8; ks++) {
            uint32_t kbyte = (uint32_t)ks * 32;
            uint32_t a0, a1, a2, a3;
            LDSM4(a0, a1, a2, a3, QsU + qOff + kbyte);
            uint32_t bfr[8][2];
            #pragma unroll
            for (int j = 0; j < 4; j++)
                LDSM4(bfr[2 * j][0], bfr[2 * j][1], bfr[2 * j + 1][0], bfr[2 * j + 1][1],
                      kcur + kOff[j] + kbyte);
            #pragma unroll
            for (int ni = 0; ni < 8; ni++)
                MMA_TF32(s[ni][0], s[ni][1], s[ni][2], s[ni][3],
                         a0, a1, a2, a3, bfr[ni][0], bfr[ni][1]);
        }
        if (kb == qb) {
            #pragma unroll
            for (int ni = 0; ni < 8; ni++) {
                int c0 = ni * 8 + tig * 2, c1 = c0 + 1;
                if (c0 > row_l0) s[ni][0] = -1e30f;
                if (c1 > row_l0) s[ni][1] = -1e30f;
                if (c0 > row_l1) s[ni][2] = -1e30f;
                if (c1 > row_l1) s[ni][3] = -1e30f;
            }
        }

        // online softmax
        float rm0 = -1e30f, rm1 = -1e30f;
        #pragma unroll
        for (int ni = 0; ni < 8; ni++) {
            rm0 = fmaxf(rm0, fmaxf(s[ni][0], s[ni][1]));
            rm1 = fmaxf(rm1, fmaxf(s[ni][2], s[ni][3]));
        }
        rm0 = fmaxf(rm0, __shfl_xor_sync(0xffffffffu, rm0, 1));
        rm0 = fmaxf(rm0, __shfl_xor_sync(0xffffffffu, rm0, 2));
        rm1 = fmaxf(rm1, __shfl_xor_sync(0xffffffffu, rm1, 1));
        rm1 = fmaxf(rm1, __shfl_xor_sync(0xffffffffu, rm1, 2));
        float mn0 = fmaxf(m0, rm0), mn1 = fmaxf(m1, rm1);
        float al0 = __expf(m0 - mn0), al1 = __expf(m1 - mn1);
        float rs0 = 0.f, rs1 = 0.f;
        #pragma unroll
        for (int ni = 0; ni < 8; ni++) {
            s[ni][0] = __expf(s[ni][0] - mn0); rs0 += s[ni][0];
            s[ni][1] = __expf(s[ni][1] - mn0); rs0 += s[ni][1];
            s[ni][2] = __expf(s[ni][2] - mn1); rs1 += s[ni][2];
            s[ni][3] = __expf(s[ni][3] - mn1); rs1 += s[ni][3];
        }
        rs0 += __shfl_xor_sync(0xffffffffu, rs0, 1);
        rs0 += __shfl_xor_sync(0xffffffffu, rs0, 2);
        rs1 += __shfl_xor_sync(0xffffffffu, rs1, 1);
        rs1 += __shfl_xor_sync(0xffffffffu, rs1, 2);
        l0 = l0 * al0 + rs0; l1 = l1 * al1 + rs1;
        m0 = mn0; m1 = mn1;
        #pragma unroll
        for (int ni = 0; ni < 8; ni++) {
            oa[ni][0] *= al0; oa[ni][1] *= al0;
            oa[ni][2] *= al1; oa[ni][3] *= al1;
        }

        // P -> per-warp smem
        #pragma unroll
        for (int ni = 0; ni < 8; ni++) {
            int cc = ni * 8 + tig * 2;
            *(float2*)&Ps[grp * PS_STR + cc]       = make_float2(s[ni][0], s[ni][1]);
            *(float2*)&Ps[(grp + 8) * PS_STR + cc] = make_float2(s[ni][2], s[ni][3]);
        }
        __syncwarp();

        // O += P @ V  (P via ldmatrix, V scalar: conflict-free lane pattern)
        #pragma unroll
        for (int ks = 0; ks < 8; ks++) {
            int k8 = ks << 3;
            uint32_t a0, a1, a2, a3;
            LDSM4(a0, a1, a2, a3, PsU + pOff + (uint32_t)ks * 32);
            #pragma unroll
            for (int ni = 0; ni < 8; ni++) {
                const float* vp = &Vcur[(k8 + tig) * VS_STR + ni * 8 + grp];
                uint32_t b0 = __float_as_uint(vp[0]);
                uint32_t b1 = __float_as_uint(vp[4 * VS_STR]);
                MMA_TF32(oa[ni][0], oa[ni][1], oa[ni][2], oa[ni][3], a0, a1, a2, a3, b0, b1);
            }
        }
        __syncwarp();
    }

    float inv0 = 1.f / l0, inv1 = 1.f / l1;
    size_t r0 = baseo + (size_t)(qb * 64 + row_l0) * D_MODEL;
    size_t r1 = baseo + (size_t)(qb * 64 + row_l1) * D_MODEL;
    #pragma unroll
    for (int ni = 0; ni < 8; ni++) {
        int cc = ni * 8 + tig * 2;
        *(float2*)(o + r0 + cc) = make_float2(oa[ni][0] * inv0, oa[ni][1] * inv0);
        *(float2*)(o + r1 + cc) = make_float2(oa[ni][2] * inv1, oa[ni][3] * inv1);
    }
}

// ---------------- launch ----------------
extern "C" void kernel_launch(void* const* d_in, const int* in_sizes, int n_in,
                              void* d_out, int out_size)
{
    const float* x  = (const float*)d_in[0];
    const float* Wq = (const float*)d_in[1];
    const float* Wk = (const float*)d_in[2];
    const float* Wv = (const float*)d_in[3];
    const float* Wo = (const float*)d_in[4];
    const float* W1 = (const float*)d_in[5];
    const float* b1 = (const float*)d_in[6];
    const float* W2 = (const float*)d_in[7];
    const float* b2 = (const float*)d_in[8];
    const float* g1 = (const float*)d_in[9];
    const float* g2 = (const float*)d_in[10];
    float* out = (float*)d_out;

    float *xn, *qkv, *attn, *x2, *hn, *f1, *wqkvT, *woT, *w1T, *w2T;
    cudaGetSymbolAddress((void**)&xn,    g_xn);
    cudaGetSymbolAddress((void**)&qkv,   g_qkv);
    cudaGetSymbolAddress((void**)&attn,  g_attn);
    cudaGetSymbolAddress((void**)&x2,    g_x2);
    cudaGetSymbolAddress((void**)&hn,    g_h);
    cudaGetSymbolAddress((void**)&f1,    g_f1);
    cudaGetSymbolAddress((void**)&wqkvT, g_wqkvT);
    cudaGetSymbolAddress((void**)&woT,   g_woT);
    cudaGetSymbolAddress((void**)&w1T,   g_w1T);
    cudaGetSymbolAddress((void**)&w2T,   g_w2T);

    const int SMEM_SZ = 4 * SM_TILE * sizeof(float);   // 73,728 B
    cudaFuncSetAttribute(gemm_mma<false, false, false>,
                         cudaFuncAttributeMaxDynamicSharedMemorySize, SMEM_SZ);
    cudaFuncSetAttribute(gemm_mma<false, false, true>,
                         cudaFuncAttributeMaxDynamicSharedMemorySize, SMEM_SZ);
    cudaFuncSetAttribute(gemm_mma<true, true, false>,
                         cudaFuncAttributeMaxDynamicSharedMemorySize, SMEM_SZ);
    cudaFuncSetAttribute(gemm_mma<true, false, true>,
                         cudaFuncAttributeMaxDynamicSharedMemorySize, SMEM_SZ);
    cudaFuncSetAttribute(attn_mma,
                         cudaFuncAttributeMaxDynamicSharedMemorySize, ATTN_SMEM);

    transpose_round<<<dim3(32, 32), 256>>>(Wq, wqkvT,                  D_MODEL, D_MODEL);
    transpose_round<<<dim3(32, 32), 256>>>(Wk, wqkvT + 1024 * D_MODEL, D_MODEL, D_MODEL);
    transpose_round<<<dim3(32, 32), 256>>>(Wv, wqkvT + 2048 * D_MODEL, D_MODEL, D_MODEL);
    transpose_round<<<dim3(32, 32), 256>>>(Wo, woT,                    D_MODEL, D_MODEL);
    transpose_round<<<dim3(128, 32), 256>>>(W1, w1T,                   D_MODEL, D_FF);
    transpose_round<<<dim3(32, 128), 256>>>(W2, w2T,                   D_FF,    D_MODEL);

    rmsnorm_kernel<<<NTOK, 256>>>(x, g1, xn);
    gemm_mma<false, false, false><<<dim3(QKV_N / 128, NTOK / 128), 256, SMEM_SZ>>>(
        xn, wqkvT, nullptr, nullptr, qkv, NTOK, QKV_N, D_MODEL);
    attn_mma<<<dim3(T_SEQ / 64, NH, BATCH), 128, ATTN_SMEM>>>(qkv, attn);
    gemm_mma<false, false, true><<<dim3(D_MODEL / 128, NTOK / 128), 256, SMEM_SZ>>>(
        attn, woT, nullptr, x, x2, NTOK, D_MODEL, D_MODEL);
    rmsnorm_kernel<<<NTOK, 256>>>(x2, g2, hn);
    gemm_mma<true, true, false><<<dim3(D_FF / 128, NTOK / 128), 256, SMEM_SZ>>>(
        hn, w1T, b1, nullptr, f1, NTOK, D_FF, D_MODEL);
    gemm_mma<true, false, true><<<dim3(D_MODEL / 128, NTOK / 128), 256, SMEM_SZ>>>(
        f1, w2T, b2, x2, out, NTOK, D_MODEL, D_FF);
}

// round 6
// speedup vs baseline: 6.1476x; 1.7437x over previous
#include <cuda_runtime.h>
#include <cuda_fp16.h>
#include <math.h>
#include <cstdint>

#define D_MODEL 1024
#define T_SEQ   2048
#define BATCH   2
#define NTOK    (BATCH * T_SEQ)   // 4096
#define D_FF    4096
#define NH      16
#define DH      64
#define QKV_N   3072

// ---------------- scratch (no allocations allowed) ----------------
__device__ __half g_xn_h  [NTOK * D_MODEL];
__device__ __half g_qkv_h [NTOK * QKV_N];
__device__ __half g_attn_h[NTOK * D_MODEL];
__device__ float  g_x2    [NTOK * D_MODEL];
__device__ __half g_hn_h  [NTOK * D_MODEL];
__device__ __half g_f1_h  [NTOK * D_FF];
__device__ __half g_wqkvT [QKV_N * D_MODEL];
__device__ __half g_woT   [D_MODEL * D_MODEL];
__device__ __half g_w1T   [D_FF * D_MODEL];
__device__ __half g_w2T   [D_MODEL * D_FF];

__device__ __forceinline__ uint32_t smem_u32(const void* p) {
    uint32_t a;
    asm("{ .reg .u64 t; cvta.to.shared.u64 t, %1; cvt.u32.u64 %0, t; }" : "=r"(a) : "l"(p));
    return a;
}
#define CP_ASYNC16(dst, src) \
    asm volatile("cp.async.cg.shared.global [%0], [%1], 16;" :: "r"(dst), "l"(src))
#define CP_COMMIT() asm volatile("cp.async.commit_group;")
#define CP_WAIT0()  asm volatile("cp.async.wait_group 0;")

#define MMA_F16(c0, c1, c2, c3, a0, a1, a2, a3, b0, b1) \
    asm volatile( \
        "mma.sync.aligned.m16n8k16.row.col.f32.f16.f16.f32 " \
        "{%0,%1,%2,%3}, {%4,%5,%6,%7}, {%8,%9}, {%0,%1,%2,%3};" \
        : "+f"(c0), "+f"(c1), "+f"(c2), "+f"(c3) \
        : "r"(a0), "r"(a1), "r"(a2), "r"(a3), "r"(b0), "r"(b1))

#define LDSM4(r0, r1, r2, r3, a) \
    asm volatile("ldmatrix.sync.aligned.m8n8.x4.shared.b16 {%0,%1,%2,%3}, [%4];" \
        : "=r"(r0), "=r"(r1), "=r"(r2), "=r"(r3) : "r"(a))
#define LDSM4T(r0, r1, r2, r3, a) \
    asm volatile("ldmatrix.sync.aligned.m8n8.x4.trans.shared.b16 {%0,%1,%2,%3}, [%4];" \
        : "=r"(r0), "=r"(r1), "=r"(r2), "=r"(r3) : "r"(a))

// ---------------- fused weight transposes: W[K][N] -> WT[N][K] (fp16) ----------------
__device__ __forceinline__ void trans_tile(
    const float* __restrict__ W, __half* __restrict__ WT, int K, int N, int n0, int k0)
{
    __shared__ float t[32][33];
    int tx = threadIdx.x & 31, ty = threadIdx.x >> 5;   // 32x8
    #pragma unroll
    for (int i = 0; i < 32; i += 8)
        t[ty + i][tx] = W[(size_t)(k0 + ty + i) * N + n0 + tx];
    __syncthreads();
    #pragma unroll
    for (int i = 0; i < 32; i += 8)
        WT[(size_t)(n0 + ty + i) * K + k0 + tx] = __float2half_rn(t[tx][ty + i]);
}

__global__ void __launch_bounds__(256) transpose_sq(
    const float* __restrict__ Wq, const float* __restrict__ Wk,
    const float* __restrict__ Wv, const float* __restrict__ Wo,
    __half* __restrict__ qkvT, __half* __restrict__ woT)
{
    int z = blockIdx.z;
    const float* src = (z == 0) ? Wq : (z == 1) ? Wk : (z == 2) ? Wv : Wo;
    __half* dst = (z < 3) ? (qkvT + (size_t)z * D_MODEL * D_MODEL) : woT;
    trans_tile(src, dst, D_MODEL, D_MODEL, blockIdx.x * 32, blockIdx.y * 32);
}

__global__ void __launch_bounds__(256) transpose_ffn(
    const float* __restrict__ W1, const float* __restrict__ W2,
    __half* __restrict__ w1T, __half* __restrict__ w2T)
{
    if (blockIdx.z == 0)
        trans_tile(W1, w1T, D_MODEL, D_FF, blockIdx.x * 32, blockIdx.y * 32);
    else
        trans_tile(W2, w2T, D_FF, D_MODEL, blockIdx.y * 32, blockIdx.x * 32);
}

// ---------------- RMSNorm (fp32 in, fp16 out) ----------------
__global__ void __launch_bounds__(256) rmsnorm_h(
    const float* __restrict__ x, const float* __restrict__ g, __half* __restrict__ y)
{
    int row = blockIdx.x;
    int tid = threadIdx.x;
    const float4* xr = (const float4*)(x + (size_t)row * D_MODEL);
    float4 v = xr[tid];
    float s = v.x * v.x + v.y * v.y + v.z * v.z + v.w * v.w;
    #pragma unroll
    for (int o = 16; o > 0; o >>= 1) s += __shfl_xor_sync(0xffffffffu, s, o);
    __shared__ float red[8];
    if ((tid & 31) == 0) red[tid >> 5] = s;
    __syncthreads();
    float tot = red[0] + red[1] + red[2] + red[3] + red[4] + red[5] + red[6] + red[7];
    float inv = rsqrtf(tot * (1.0f / D_MODEL) + 1e-6f);
    float4 gv = ((const float4*)g)[tid];
    __half2* yp = (__half2*)(y + (size_t)row * D_MODEL + tid * 4);
    yp[0] = __floats2half2_rn(v.x * inv * gv.x, v.y * inv * gv.y);
    yp[1] = __floats2half2_rn(v.z * inv * gv.z, v.w * inv * gv.w);
}

// ---------------- fp16 mma GEMM: C[M,N] = A[M,K] @ BT[N,K]^T ----------------
// Block 128x128, 8 warps (2M x 4N), warp 64x32 = 4x4 m16n8k16 per k16.
// smem: half tiles 128 x 32 (stride 40 halfs), double buffered.
#define HSTR 40
#define HTILE (128 * HSTR)           // halfs per buffer
#define HBUF_B (HTILE * 2)           // bytes per buffer
#define GEMM_SMEM (4 * HTILE * 2)    // 40,960 B

template<bool BIAS, bool GELU_ACT, bool RES, bool HOUT>
__global__ void __launch_bounds__(256) gemm_h(
    const __half* __restrict__ A, const __half* __restrict__ BT,
    const float* __restrict__ bias, const float* __restrict__ res,
    void* __restrict__ Cv, int M, int N, int K)
{
    extern __shared__ __half smh[];
    __half* As = smh;                 // 2 buffers
    __half* Bs = smh + 2 * HTILE;     // 2 buffers

    int tid = threadIdx.x;
    int lane = tid & 31, wid = tid >> 5;
    int warpM = (wid & 1) * 64;
    int warpN = (wid >> 1) * 32;
    int grp = lane >> 2, tig = lane & 3;
    int m8 = lane >> 3, l8 = lane & 7;
    int bn = blockIdx.x, bm = blockIdx.y;

    uint32_t AsU = smem_u32(As), BsU = smem_u32(Bs);

    int arow = tid >> 2, aseg = (tid & 3) << 3;   // 64 rows/step, 8-half segs
    const __half* Aptr = A  + (size_t)bm * 128 * K + (size_t)arow * K + aseg;
    const __half* Bptr = BT + (size_t)bn * 128 * K + (size_t)arow * K + aseg;
    uint32_t dA = AsU + (uint32_t)(arow * HSTR + aseg) * 2;
    uint32_t dB = BsU + (uint32_t)(arow * HSTR + aseg) * 2;

    // ldmatrix byte offsets
    uint32_t aOff[4], bOff[2];
    #pragma unroll
    for (int mi = 0; mi < 4; mi++)
        aOff[mi] = (uint32_t)((warpM + mi * 16 + (lane & 15)) * HSTR
                              + ((lane >> 4) << 3)) * 2;
    #pragma unroll
    for (int j = 0; j < 2; j++)
        bOff[j] = (uint32_t)((warpN + j * 16 + ((m8 >> 1) << 3) + l8) * HSTR
                              + ((m8 & 1) << 3)) * 2;

    float acc[4][4][4];
    #pragma unroll
    for (int mi = 0; mi < 4; mi++)
        #pragma unroll
        for (int ni = 0; ni < 4; ni++)
            #pragma unroll
            for (int r = 0; r < 4; r++) acc[mi][ni][r] = 0.f;

    int nch = K >> 5;

    #pragma unroll
    for (int t = 0; t < 2; t++) {
        CP_ASYNC16(dA + (uint32_t)(t * 64 * HSTR) * 2, Aptr + (size_t)t * 64 * K);
        CP_ASYNC16(dB + (uint32_t)(t * 64 * HSTR) * 2, Bptr + (size_t)t * 64 * K);
    }
    CP_COMMIT();

    for (int c = 0; c < nch; c++) {
        CP_WAIT0();
        __syncthreads();
        if (c + 1 < nch) {
            int k0 = (c + 1) << 5;
            uint32_t boff = (uint32_t)(((c + 1) & 1)) * HBUF_B;
            #pragma unroll
            for (int t = 0; t < 2; t++) {
                CP_ASYNC16(dA + boff + (uint32_t)(t * 64 * HSTR) * 2,
                           Aptr + (size_t)t * 64 * K + k0);
                CP_ASYNC16(dB + boff + (uint32_t)(t * 64 * HSTR) * 2,
                           Bptr + (size_t)t * 64 * K + k0);
            }
            CP_COMMIT();
        }
        uint32_t abase = AsU + (uint32_t)(c & 1) * HBUF_B;
        uint32_t bbase = BsU + (uint32_t)(c & 1) * HBUF_B;
        #pragma unroll
        for (int kk = 0; kk < 2; kk++) {
            uint32_t kb = (uint32_t)kk * 32;     // 16 halfs
            uint32_t af[4][4], bf[4][2];
            #pragma unroll
            for (int mi = 0; mi < 4; mi++)
                LDSM4(af[mi][0], af[mi][1], af[mi][2], af[mi][3],
                      abase + aOff[mi] + kb);
            #pragma unroll
            for (int j = 0; j < 2; j++)
                LDSM4(bf[2 * j][0], bf[2 * j][1], bf[2 * j + 1][0], bf[2 * j + 1][1],
                      bbase + bOff[j] + kb);
            #pragma unroll
            for (int mi = 0; mi < 4; mi++)
                #pragma unroll
                for (int ni = 0; ni < 4; ni++)
                    MMA_F16(acc[mi][ni][0], acc[mi][ni][1], acc[mi][ni][2], acc[mi][ni][3],
                            af[mi][0], af[mi][1], af[mi][2], af[mi][3],
                            bf[ni][0], bf[ni][1]);
        }
        __syncthreads();
    }

    #pragma unroll
    for (int mi = 0; mi < 4; mi++) {
        #pragma unroll
        for (int half = 0; half < 2; half++) {
            size_t r = (size_t)bm * 128 + warpM + mi * 16 + grp + half * 8;
            #pragma unroll
            for (int ni = 0; ni < 4; ni++) {
                int cg = bn * 128 + warpN + ni * 8 + tig * 2;
                float v0 = acc[mi][ni][half * 2 + 0];
                float v1 = acc[mi][ni][half * 2 + 1];
                if (BIAS) { v0 += bias[cg]; v1 += bias[cg + 1]; }
                if (GELU_ACT) {
                    v0 = 0.5f * v0 * (1.0f + erff(v0 * 0.70710678118654752f));
                    v1 = 0.5f * v1 * (1.0f + erff(v1 * 0.70710678118654752f));
                }
                size_t idx = r * (size_t)N + cg;
                if (RES) {
                    float2 r2 = *(const float2*)(res + idx);
                    v0 += r2.x; v1 += r2.y;
                }
                if (HOUT) {
                    *(__half2*)((__half*)Cv + idx) = __floats2half2_rn(v0, v1);
                } else {
                    float2 o2; o2.x = v0; o2.y = v1;
                    *(float2*)((float*)Cv + idx) = o2;
                }
            }
        }
    }
}

// ---------------- fp16 mma causal flash attention ----------------
// 64 q-rows/CTA, 4 warps x 16 rows. cp.async double-buffered K/V.
#define ASTR 72
#define Q_HL (64 * ASTR)
#define K_HL (64 * ASTR)
#define V_HL (64 * ASTR)
#define P_HL (16 * ASTR)
#define ATTN_SMEM ((Q_HL + 2 * K_HL + 2 * V_HL + 4 * P_HL) * 2)

__global__ void __launch_bounds__(128) attn_h(
    const __half* __restrict__ qkv, __half* __restrict__ o)
{
    extern __shared__ __half smh[];
    __half* Qs = smh;
    __half* Ks = Qs + Q_HL;           // 2 buffers
    __half* Vs = Ks + 2 * K_HL;       // 2 buffers
    int tid = threadIdx.x;
    int lane = tid & 31, wid = tid >> 5;
    int grp = lane >> 2, tig = lane & 3;
    int m8 = lane >> 3, l8 = lane & 7;
    __half* Ps = Vs + 2 * V_HL + wid * P_HL;

    uint32_t QsU = smem_u32(Qs), KsU = smem_u32(Ks), VsU = smem_u32(Vs);
    uint32_t PsU = smem_u32(Ps);

    int qb = gridDim.x - 1 - blockIdx.x;   // heavy tiles first
    int h = blockIdx.y, b = blockIdx.z;
    size_t base  = (size_t)b * T_SEQ * QKV_N + h * DH;
    size_t baseo = (size_t)b * T_SEQ * D_MODEL + h * DH;
    const __half* qg = qkv + base;
    const __half* kg = qkv + base + D_MODEL;
    const __half* vg = qkv + base + 2 * D_MODEL;

    // ldmatrix offsets (bytes)
    uint32_t qOff = (uint32_t)((wid * 16 + (lane & 15)) * ASTR + ((lane >> 4) << 3)) * 2;
    uint32_t kOff[4], vOff[4];
    #pragma unroll
    for (int j = 0; j < 4; j++) {
        kOff[j] = (uint32_t)((j * 16 + ((m8 >> 1) << 3) + l8) * ASTR
                             + ((m8 & 1) << 3)) * 2;
        vOff[j] = (uint32_t)((((m8 & 1) << 3) + l8) * ASTR
                             + j * 16 + ((m8 >> 1) << 3)) * 2;
    }
    uint32_t pOff = (uint32_t)((lane & 15) * ASTR + ((lane >> 4) << 3)) * 2;

    // cp.async loader coords: 64 rows x 8 segs of 8 halfs
    int ldrow = tid >> 3, ldseg = (tid & 7) << 3;   // 16 rows/step

    // Q tile (raw half; 1/8 scale folded into S)
    #pragma unroll
    for (int t = 0; t < 4; t++) {
        int r = ldrow + t * 16;
        CP_ASYNC16(QsU + (uint32_t)(r * ASTR + ldseg) * 2,
                   qg + (size_t)(qb * 64 + r) * QKV_N + ldseg);
    }
    // K/V tile 0
    #pragma unroll
    for (int t = 0; t < 4; t++) {
        int r = ldrow + t * 16;
        CP_ASYNC16(KsU + (uint32_t)(r * ASTR + ldseg) * 2, kg + (size_t)r * QKV_N + ldseg);
        CP_ASYNC16(VsU + (uint32_t)(r * ASTR + ldseg) * 2, vg + (size_t)r * QKV_N + ldseg);
    }
    CP_COMMIT();

    float m0 = -1e30f, m1 = -1e30f, l0 = 0.f, l1 = 0.f;
    float oa[8][4];
    #pragma unroll
    for (int ni = 0; ni < 8; ni++)
        #pragma unroll
        for (int r = 0; r < 4; r++) oa[ni][r] = 0.f;

    int row_l0 = wid * 16 + grp;
    int row_l1 = row_l0 + 8;

    for (int kb = 0; kb <= qb; kb++) {
        CP_WAIT0();
        __syncthreads();
        if (kb < qb) {
            uint32_t kbuf = KsU + (uint32_t)(((kb + 1) & 1) * K_HL) * 2;
            uint32_t vbuf = VsU + (uint32_t)(((kb + 1) & 1) * V_HL) * 2;
            const __half* kgn = kg + (size_t)(kb + 1) * 64 * QKV_N;
            const __half* vgn = vg + (size_t)(kb + 1) * 64 * QKV_N;
            #pragma unroll
            for (int t = 0; t < 4; t++) {
                int r = ldrow + t * 16;
                CP_ASYNC16(kbuf + (uint32_t)(r * ASTR + ldseg) * 2,
                           kgn + (size_t)r * QKV_N + ldseg);
                CP_ASYNC16(vbuf + (uint32_t)(r * ASTR + ldseg) * 2,
                           vgn + (size_t)r * QKV_N + ldseg);
            }
            CP_COMMIT();
        }
        uint32_t kcur = KsU + (uint32_t)((kb & 1) * K_HL) * 2;
        uint32_t vcur = VsU + (uint32_t)((kb & 1) * V_HL) * 2;

        // S = Q @ K^T (4 k16 steps over Dh=64)
        float s[8][4];
        #pragma unroll
        for (int ni = 0; ni < 8; ni++)
            #pragma unroll
            for (int r = 0; r < 4; r++) s[ni][r] = 0.f;
        #pragma unroll
        for (int ks = 0; ks < 4; ks++) {
            uint32_t kbyte = (uint32_t)ks * 32;
            uint32_t a0, a1, a2, a3;
            LDSM4(a0, a1, a2, a3, QsU + qOff + kbyte);
            uint32_t bfr[8][2];
            #pragma unroll
            for (int j = 0; j < 4; j++)
                LDSM4(bfr[2 * j][0], bfr[2 * j][1], bfr[2 * j + 1][0], bfr[2 * j + 1][1],
                      kcur + kOff[j] + kbyte);
            #pragma unroll
            for (int ni = 0; ni < 8; ni++)
                MMA_F16(s[ni][0], s[ni][1], s[ni][2], s[ni][3],
                        a0, a1, a2, a3, bfr[ni][0], bfr[ni][1]);
        }
        #pragma unroll
        for (int ni = 0; ni < 8; ni++)
            #pragma unroll
            for (int r = 0; r < 4; r++) s[ni][r] *= 0.125f;
        if (kb == qb) {
            #pragma unroll
            for (int ni = 0; ni < 8; ni++) {
                int c0 = ni * 8 + tig * 2, c1 = c0 + 1;
                if (c0 > row_l0) s[ni][0] = -1e30f;
                if (c1 > row_l0) s[ni][1] = -1e30f;
                if (c0 > row_l1) s[ni][2] = -1e30f;
                if (c1 > row_l1) s[ni][3] = -1e30f;
            }
        }

        // online softmax
        float rm0 = -1e30f, rm1 = -1e30f;
        #pragma unroll
        for (int ni = 0; ni < 8; ni++) {
            rm0 = fmaxf(rm0, fmaxf(s[ni][0], s[ni][1]));
            rm1 = fmaxf(rm1, fmaxf(s[ni][2], s[ni][3]));
        }
        rm0 = fmaxf(rm0, __shfl_xor_sync(0xffffffffu, rm0, 1));
        rm0 = fmaxf(rm0, __shfl_xor_sync(0xffffffffu, rm0, 2));
        rm1 = fmaxf(rm1, __shfl_xor_sync(0xffffffffu, rm1, 1));
        rm1 = fmaxf(rm1, __shfl_xor_sync(0xffffffffu, rm1, 2));
        float mn0 = fmaxf(m0, rm0), mn1 = fmaxf(m1, rm1);
        float al0 = __expf(m0 - mn0), al1 = __expf(m1 - mn1);
        float rs0 = 0.f, rs1 = 0.f;
        #pragma unroll
        for (int ni = 0; ni < 8; ni++) {
            s[ni][0] = __expf(s[ni][0] - mn0); rs0 += s[ni][0];
            s[ni][1] = __expf(s[ni][1] - mn0); rs0 += s[ni][1];
            s[ni][2] = __expf(s[ni][2] - mn1); rs1 += s[ni][2];
            s[ni][3] = __expf(s[ni][3] - mn1); rs1 += s[ni][3];
        }
        rs0 += __shfl_xor_sync(0xffffffffu, rs0, 1);
        rs0 += __shfl_xor_sync(0xffffffffu, rs0, 2);
        rs1 += __shfl_xor_sync(0xffffffffu, rs1, 1);
        rs1 += __shfl_xor_sync(0xffffffffu, rs1, 2);
        l0 = l0 * al0 + rs0; l1 = l1 * al1 + rs1;
        m0 = mn0; m1 = mn1;
        #pragma unroll
        for (int ni = 0; ni < 8; ni++) {
            oa[ni][0] *= al0; oa[ni][1] *= al0;
            oa[ni][2] *= al1; oa[ni][3] *= al1;
        }

        // P -> per-warp smem (fp16)
        #pragma unroll
        for (int ni = 0; ni < 8; ni++) {
            int cc = ni * 8 + tig * 2;
            *(__half2*)(Ps + grp * ASTR + cc)       = __floats2half2_rn(s[ni][0], s[ni][1]);
            *(__half2*)(Ps + (grp + 8) * ASTR + cc) = __floats2half2_rn(s[ni][2], s[ni][3]);
        }
        __syncwarp();

        // O += P @ V (V via ldmatrix.trans)
        #pragma unroll
        for (int ks = 0; ks < 4; ks++) {
            uint32_t a0, a1, a2, a3;
            LDSM4(a0, a1, a2, a3, PsU + pOff + (uint32_t)ks * 32);
            uint32_t vrow = (uint32_t)(ks * 16 * ASTR) * 2;
            uint32_t bfr[8][2];
            #pragma unroll
            for (int j = 0; j < 4; j++)
                LDSM4T(bfr[2 * j][0], bfr[2 * j][1], bfr[2 * j + 1][0], bfr[2 * j + 1][1],
                       vcur + vrow + vOff[j]);
            #pragma unroll
            for (int ni = 0; ni < 8; ni++)
                MMA_F16(oa[ni][0], oa[ni][1], oa[ni][2], oa[ni][3],
                        a0, a1, a2, a3, bfr[ni][0], bfr[ni][1]);
        }
        __syncwarp();
    }

    float inv0 = 1.f / l0, inv1 = 1.f / l1;
    size_t r0 = baseo + (size_t)(qb * 64 + row_l0) * D_MODEL;
    size_t r1 = baseo + (size_t)(qb * 64 + row_l1) * D_MODEL;
    #pragma unroll
    for (int ni = 0; ni < 8; ni++) {
        int cc = ni * 8 + tig * 2;
        *(__half2*)(o + r0 + cc) = __floats2half2_rn(oa[ni][0] * inv0, oa[ni][1] * inv0);
        *(__half2*)(o + r1 + cc) = __floats2half2_rn(oa[ni][2] * inv1, oa[ni][3] * inv1);
    }
}

// ---------------- launch ----------------
extern "C" void kernel_launch(void* const* d_in, const int* in_sizes, int n_in,
                              void* d_out, int out_size)
{
    const float* x  = (const float*)d_in[0];
    const float* Wq = (const float*)d_in[1];
    const float* Wk = (const float*)d_in[2];
    const float* Wv = (const float*)d_in[3];
    const float* Wo = (const float*)d_in[4];
    const float* W1 = (const float*)d_in[5];
    const float* b1 = (const float*)d_in[6];
    const float* W2 = (const float*)d_in[7];
    const float* b2 = (const float*)d_in[8];
    const float* g1 = (const float*)d_in[9];
    const float* g2 = (const float*)d_in[10];
    float* out = (float*)d_out;

    __half *xn, *qkv, *attn, *hn, *f1, *wqkvT, *woT, *w1T, *w2T;
    float* x2;
    cudaGetSymbolAddress((void**)&xn,    g_xn_h);
    cudaGetSymbolAddress((void**)&qkv,   g_qkv_h);
    cudaGetSymbolAddress((void**)&attn,  g_attn_h);
    cudaGetSymbolAddress((void**)&x2,    g_x2);
    cudaGetSymbolAddress((void**)&hn,    g_hn_h);
    cudaGetSymbolAddress((void**)&f1,    g_f1_h);
    cudaGetSymbolAddress((void**)&wqkvT, g_wqkvT);
    cudaGetSymbolAddress((void**)&woT,   g_woT);
    cudaGetSymbolAddress((void**)&w1T,   g_w1T);
    cudaGetSymbolAddress((void**)&w2T,   g_w2T);

    cudaFuncSetAttribute(attn_h, cudaFuncAttributeMaxDynamicSharedMemorySize, ATTN_SMEM);

    // 1-2: weight transposes (fp16)
    transpose_sq <<<dim3(32, 32, 4), 256>>>(Wq, Wk, Wv, Wo, wqkvT, woT);
    transpose_ffn<<<dim3(128, 32, 2), 256>>>(W1, W2, w1T, w2T);
    // 3: x1 = rmsnorm(x, g1) -> fp16
    rmsnorm_h<<<NTOK, 256>>>(x, g1, xn);
    // 4: qkv = x1 @ [Wq|Wk|Wv] -> fp16
    gemm_h<false, false, false, true><<<dim3(QKV_N / 128, NTOK / 128), 256, GEMM_SMEM>>>(
        xn, wqkvT, nullptr, nullptr, qkv, NTOK, QKV_N, D_MODEL);
    // 5: causal attention -> fp16
    attn_h<<<dim3(T_SEQ / 64, NH, BATCH), 128, ATTN_SMEM>>>(qkv, attn);
    // 6: x2 = x + attn @ Wo -> fp32   (this is the ncu-captured launch)
    gemm_h<false, false, true, false><<<dim3(D_MODEL / 128, NTOK / 128), 256, GEMM_SMEM>>>(
        attn, woT, nullptr, x, x2, NTOK, D_MODEL, D_MODEL);
    // 7: h = rmsnorm(x2, g2) -> fp16
    rmsnorm_h<<<NTOK, 256>>>(x2, g2, hn);
    // 8: f1 = gelu(h @ W1 + b1) -> fp16
    gemm_h<true, true, false, true><<<dim3(D_FF / 128, NTOK / 128), 256, GEMM_SMEM>>>(
        hn, w1T, b1, nullptr, f1, NTOK, D_FF, D_MODEL);
    // 9: out = x2 + f1 @ W2 + b2 -> fp32
    gemm_h<true, false, true, false><<<dim3(D_MODEL / 128, NTOK / 128), 256, GEMM_SMEM>>>(
        f1, w2T, b2, x2, out, NTOK, D_MODEL, D_FF);
}

// round 7
// speedup vs baseline: 6.3897x; 1.0394x over previous
#include <cuda_runtime.h>
#include <cuda_fp16.h>
#include <math.h>
#include <cstdint>

#define D_MODEL 1024
#define T_SEQ   2048
#define BATCH   2
#define NTOK    (BATCH * T_SEQ)   // 4096
#define D_FF    4096
#define NH      16
#define DH      64
#define QKV_N   3072

// ---------------- scratch (no allocations allowed) ----------------
__device__ __half g_xn_h  [NTOK * D_MODEL];
__device__ __half g_qkv_h [NTOK * QKV_N];
__device__ __half g_attn_h[NTOK * D_MODEL];
__device__ float  g_x2    [NTOK * D_MODEL];
__device__ __half g_hn_h  [NTOK * D_MODEL];
__device__ __half g_f1_h  [NTOK * D_FF];
__device__ __half g_wqkvT [QKV_N * D_MODEL];
__device__ __half g_woT   [D_MODEL * D_MODEL];
__device__ __half g_w1T   [D_FF * D_MODEL];
__device__ __half g_w2T   [D_MODEL * D_FF];

__device__ __forceinline__ uint32_t smem_u32(const void* p) {
    uint32_t a;
    asm("{ .reg .u64 t; cvta.to.shared.u64 t, %1; cvt.u32.u64 %0, t; }" : "=r"(a) : "l"(p));
    return a;
}
#define CP_ASYNC16(dst, src) \
    asm volatile("cp.async.cg.shared.global [%0], [%1], 16;" :: "r"(dst), "l"(src))
#define CP_COMMIT() asm volatile("cp.async.commit_group;")
#define CP_WAIT0()  asm volatile("cp.async.wait_group 0;")
#define CP_WAIT1()  asm volatile("cp.async.wait_group 1;")

#define MMA_F16(c0, c1, c2, c3, a0, a1, a2, a3, b0, b1) \
    asm volatile( \
        "mma.sync.aligned.m16n8k16.row.col.f32.f16.f16.f32 " \
        "{%0,%1,%2,%3}, {%4,%5,%6,%7}, {%8,%9}, {%0,%1,%2,%3};" \
        : "+f"(c0), "+f"(c1), "+f"(c2), "+f"(c3) \
        : "r"(a0), "r"(a1), "r"(a2), "r"(a3), "r"(b0), "r"(b1))

#define LDSM4(r0, r1, r2, r3, a) \
    asm volatile("ldmatrix.sync.aligned.m8n8.x4.shared.b16 {%0,%1,%2,%3}, [%4];" \
        : "=r"(r0), "=r"(r1), "=r"(r2), "=r"(r3) : "r"(a))
#define LDSM4T(r0, r1, r2, r3, a) \
    asm volatile("ldmatrix.sync.aligned.m8n8.x4.trans.shared.b16 {%0,%1,%2,%3}, [%4];" \
        : "=r"(r0), "=r"(r1), "=r"(r2), "=r"(r3) : "r"(a))

// ---------------- fused weight transposes: W[K][N] -> WT[N][K] (fp16) ----------------
__device__ __forceinline__ void trans_tile(
    const float* __restrict__ W, __half* __restrict__ WT, int K, int N, int n0, int k0)
{
    __shared__ float t[32][33];
    int tx = threadIdx.x & 31, ty = threadIdx.x >> 5;   // 32x8
    #pragma unroll
    for (int i = 0; i < 32; i += 8)
        t[ty + i][tx] = W[(size_t)(k0 + ty + i) * N + n0 + tx];
    __syncthreads();
    #pragma unroll
    for (int i = 0; i < 32; i += 8)
        WT[(size_t)(n0 + ty + i) * K + k0 + tx] = __float2half_rn(t[tx][ty + i]);
}

__global__ void __launch_bounds__(256) transpose_sq(
    const float* __restrict__ Wq, const float* __restrict__ Wk,
    const float* __restrict__ Wv, const float* __restrict__ Wo,
    __half* __restrict__ qkvT, __half* __restrict__ woT)
{
    int z = blockIdx.z;
    const float* src = (z == 0) ? Wq : (z == 1) ? Wk : (z == 2) ? Wv : Wo;
    __half* dst = (z < 3) ? (qkvT + (size_t)z * D_MODEL * D_MODEL) : woT;
    trans_tile(src, dst, D_MODEL, D_MODEL, blockIdx.x * 32, blockIdx.y * 32);
}

__global__ void __launch_bounds__(256) transpose_ffn(
    const float* __restrict__ W1, const float* __restrict__ W2,
    __half* __restrict__ w1T, __half* __restrict__ w2T)
{
    if (blockIdx.z == 0)
        trans_tile(W1, w1T, D_MODEL, D_FF, blockIdx.x * 32, blockIdx.y * 32);
    else
        trans_tile(W2, w2T, D_FF, D_MODEL, blockIdx.y * 32, blockIdx.x * 32);
}

// ---------------- RMSNorm (fp32 in, fp16 out) ----------------
__global__ void __launch_bounds__(256) rmsnorm_h(
    const float* __restrict__ x, const float* __restrict__ g, __half* __restrict__ y)
{
    int row = blockIdx.x;
    int tid = threadIdx.x;
    const float4* xr = (const float4*)(x + (size_t)row * D_MODEL);
    float4 v = xr[tid];
    float s = v.x * v.x + v.y * v.y + v.z * v.z + v.w * v.w;
    #pragma unroll
    for (int o = 16; o > 0; o >>= 1) s += __shfl_xor_sync(0xffffffffu, s, o);
    __shared__ float red[8];
    if ((tid & 31) == 0) red[tid >> 5] = s;
    __syncthreads();
    float tot = red[0] + red[1] + red[2] + red[3] + red[4] + red[5] + red[6] + red[7];
    float inv = rsqrtf(tot * (1.0f / D_MODEL) + 1e-6f);
    float4 gv = ((const float4*)g)[tid];
    __half2* yp = (__half2*)(y + (size_t)row * D_MODEL + tid * 4);
    yp[0] = __floats2half2_rn(v.x * inv * gv.x, v.y * inv * gv.y);
    yp[1] = __floats2half2_rn(v.z * inv * gv.z, v.w * inv * gv.w);
}

// ---------------- fp16 mma GEMM: 3-stage cp.async pipeline, K-chunk 64 ----------------
// Block 128x128, 8 warps (2M x 4N), warp 64x32; 4 k16 steps per chunk.
#define KC 64
#define HSTR 72
#define STAGE_HL (128 * HSTR)            // halfs per operand per stage
#define STAGE_B  (STAGE_HL * 2)          // 18,432 bytes
#define GEMM_SMEM (3 * 2 * STAGE_B)      // 110,592 bytes

template<bool BIAS, bool GELU_ACT, bool RES, bool HOUT>
__global__ void __launch_bounds__(256) gemm_h(
    const __half* __restrict__ A, const __half* __restrict__ BT,
    const float* __restrict__ bias, const float* __restrict__ res,
    void* __restrict__ Cv, int M, int N, int K)
{
    extern __shared__ __half smh[];
    uint32_t AsU = smem_u32(smh);
    uint32_t BsU = AsU + 3 * STAGE_B;

    int tid = threadIdx.x;
    int lane = tid & 31, wid = tid >> 5;
    int warpM = (wid & 1) * 64;
    int warpN = (wid >> 1) * 32;
    int grp = lane >> 2, tig = lane & 3;
    int m8 = lane >> 3, l8 = lane & 7;
    int bn = blockIdx.x, bm = blockIdx.y;

    // loader: 128 rows x 64 halfs per operand per stage; 4 cp.async each
    int ldrow = tid >> 3;                // 0..31, step 32
    int ldseg = (tid & 7) << 3;          // 0..56 halfs
    const __half* Aptr = A  + (size_t)bm * 128 * K + (size_t)ldrow * K + ldseg;
    const __half* Bptr = BT + (size_t)bn * 128 * K + (size_t)ldrow * K + ldseg;
    uint32_t dA = AsU + (uint32_t)(ldrow * HSTR + ldseg) * 2;
    uint32_t dB = BsU + (uint32_t)(ldrow * HSTR + ldseg) * 2;

    // ldmatrix byte offsets
    uint32_t aOff[4], bOff[2];
    #pragma unroll
    for (int mi = 0; mi < 4; mi++)
        aOff[mi] = (uint32_t)((warpM + mi * 16 + (lane & 15)) * HSTR
                              + ((lane >> 4) << 3)) * 2;
    #pragma unroll
    for (int j = 0; j < 2; j++)
        bOff[j] = (uint32_t)((warpN + j * 16 + ((m8 >> 1) << 3) + l8) * HSTR
                              + ((m8 & 1) << 3)) * 2;

    float acc[4][4][4];
    #pragma unroll
    for (int mi = 0; mi < 4; mi++)
        #pragma unroll
        for (int ni = 0; ni < 4; ni++)
            #pragma unroll
            for (int r = 0; r < 4; r++) acc[mi][ni][r] = 0.f;

    int nch = K / KC;

    // prologue: stages 0 and 1
    #pragma unroll
    for (int s = 0; s < 2; s++) {
        uint32_t so = (uint32_t)s * STAGE_B;
        int k0 = s * KC;
        #pragma unroll
        for (int t = 0; t < 4; t++) {
            CP_ASYNC16(dA + so + (uint32_t)(t * 32 * HSTR) * 2,
                       Aptr + (size_t)t * 32 * K + k0);
            CP_ASYNC16(dB + so + (uint32_t)(t * 32 * HSTR) * 2,
                       Bptr + (size_t)t * 32 * K + k0);
        }
        CP_COMMIT();
    }

    int stage = 0;
    for (int c = 0; c < nch; c++) {
        if (c + 1 < nch) { CP_WAIT1(); } else { CP_WAIT0(); }
        __syncthreads();
        if (c + 2 < nch) {
            int sn = stage;                    // (c+2)%3 == stage after 2 incs; reuse slot freed
            sn = stage - 1; if (sn < 0) sn += 3;   // (c+2)%3 = (c-1)%3
            uint32_t so = (uint32_t)sn * STAGE_B;
            int k0 = (c + 2) * KC;
            #pragma unroll
            for (int t = 0; t < 4; t++) {
                CP_ASYNC16(dA + so + (uint32_t)(t * 32 * HSTR) * 2,
                           Aptr + (size_t)t * 32 * K + k0);
                CP_ASYNC16(dB + so + (uint32_t)(t * 32 * HSTR) * 2,
                           Bptr + (size_t)t * 32 * K + k0);
            }
            CP_COMMIT();
        }
        uint32_t abase = AsU + (uint32_t)stage * STAGE_B;
        uint32_t bbase = BsU + (uint32_t)stage * STAGE_B;
        #pragma unroll
        for (int kk = 0; kk < 4; kk++) {
            uint32_t kb = (uint32_t)kk * 32;   // 16 halfs = 32 B
            uint32_t af[4][4], bf[4][2];
            #pragma unroll
            for (int mi = 0; mi < 4; mi++)
                LDSM4(af[mi][0], af[mi][1], af[mi][2], af[mi][3],
                      abase + aOff[mi] + kb);
            #pragma unroll
            for (int j = 0; j < 2; j++)
                LDSM4(bf[2 * j][0], bf[2 * j][1], bf[2 * j + 1][0], bf[2 * j + 1][1],
                      bbase + bOff[j] + kb);
            #pragma unroll
            for (int mi = 0; mi < 4; mi++)
                #pragma unroll
                for (int ni = 0; ni < 4; ni++)
                    MMA_F16(acc[mi][ni][0], acc[mi][ni][1], acc[mi][ni][2], acc[mi][ni][3],
                            af[mi][0], af[mi][1], af[mi][2], af[mi][3],
                            bf[ni][0], bf[ni][1]);
        }
        stage++; if (stage == 3) stage = 0;
    }

    #pragma unroll
    for (int mi = 0; mi < 4; mi++) {
        #pragma unroll
        for (int half = 0; half < 2; half++) {
            size_t r = (size_t)bm * 128 + warpM + mi * 16 + grp + half * 8;
            #pragma unroll
            for (int ni = 0; ni < 4; ni++) {
                int cg = bn * 128 + warpN + ni * 8 + tig * 2;
                float v0 = acc[mi][ni][half * 2 + 0];
                float v1 = acc[mi][ni][half * 2 + 1];
                if (BIAS) { v0 += bias[cg]; v1 += bias[cg + 1]; }
                if (GELU_ACT) {
                    v0 = 0.5f * v0 * (1.0f + erff(v0 * 0.70710678118654752f));
                    v1 = 0.5f * v1 * (1.0f + erff(v1 * 0.70710678118654752f));
                }
                size_t idx = r * (size_t)N + cg;
                if (RES) {
                    float2 r2 = *(const float2*)(res + idx);
                    v0 += r2.x; v1 += r2.y;
                }
                if (HOUT) {
                    *(__half2*)((__half*)Cv + idx) = __floats2half2_rn(v0, v1);
                } else {
                    float2 o2; o2.x = v0; o2.y = v1;
                    *(float2*)((float*)Cv + idx) = o2;
                }
            }
        }
    }
}

// ---------------- fp16 mma causal flash attention ----------------
#define ASTR 72
#define Q_HL (64 * ASTR)
#define K_HL (64 * ASTR)
#define V_HL (64 * ASTR)
#define P_HL (16 * ASTR)
#define ATTN_SMEM ((Q_HL + 2 * K_HL + 2 * V_HL + 4 * P_HL) * 2)

__global__ void __launch_bounds__(128) attn_h(
    const __half* __restrict__ qkv, __half* __restrict__ o)
{
    extern __shared__ __half smh[];
    __half* Qs = smh;
    __half* Ks = Qs + Q_HL;           // 2 buffers
    __half* Vs = Ks + 2 * K_HL;       // 2 buffers
    int tid = threadIdx.x;
    int lane = tid & 31, wid = tid >> 5;
    int grp = lane >> 2, tig = lane & 3;
    int m8 = lane >> 3, l8 = lane & 7;
    __half* Ps = Vs + 2 * V_HL + wid * P_HL;

    uint32_t QsU = smem_u32(Qs), KsU = smem_u32(Ks), VsU = smem_u32(Vs);
    uint32_t PsU = smem_u32(Ps);

    int qb = gridDim.x - 1 - blockIdx.x;   // heavy tiles first
    int h = blockIdx.y, b = blockIdx.z;
    size_t base  = (size_t)b * T_SEQ * QKV_N + h * DH;
    size_t baseo = (size_t)b * T_SEQ * D_MODEL + h * DH;
    const __half* qg = qkv + base;
    const __half* kg = qkv + base + D_MODEL;
    const __half* vg = qkv + base + 2 * D_MODEL;

    uint32_t qOff = (uint32_t)((wid * 16 + (lane & 15)) * ASTR + ((lane >> 4) << 3)) * 2;
    uint32_t kOff[4], vOff[4];
    #pragma unroll
    for (int j = 0; j < 4; j++) {
        kOff[j] = (uint32_t)((j * 16 + ((m8 >> 1) << 3) + l8) * ASTR
                             + ((m8 & 1) << 3)) * 2;
        vOff[j] = (uint32_t)((((m8 & 1) << 3) + l8) * ASTR
                             + j * 16 + ((m8 >> 1) << 3)) * 2;
    }
    uint32_t pOff = (uint32_t)((lane & 15) * ASTR + ((lane >> 4) << 3)) * 2;

    int ldrow = tid >> 3, ldseg = (tid & 7) << 3;   // 16 rows/step

    #pragma unroll
    for (int t = 0; t < 4; t++) {
        int r = ldrow + t * 16;
        CP_ASYNC16(QsU + (uint32_t)(r * ASTR + ldseg) * 2,
                   qg + (size_t)(qb * 64 + r) * QKV_N + ldseg);
    }
    #pragma unroll
    for (int t = 0; t < 4; t++) {
        int r = ldrow + t * 16;
        CP_ASYNC16(KsU + (uint32_t)(r * ASTR + ldseg) * 2, kg + (size_t)r * QKV_N + ldseg);
        CP_ASYNC16(VsU + (uint32_t)(r * ASTR + ldseg) * 2, vg + (size_t)r * QKV_N + ldseg);
    }
    CP_COMMIT();

    float m0 = -1e30f, m1 = -1e30f, l0 = 0.f, l1 = 0.f;
    float oa[8][4];
    #pragma unroll
    for (int ni = 0; ni < 8; ni++)
        #pragma unroll
        for (int r = 0; r < 4; r++) oa[ni][r] = 0.f;

    int row_l0 = wid * 16 + grp;
    int row_l1 = row_l0 + 8;

    for (int kb = 0; kb <= qb; kb++) {
        CP_WAIT0();
        __syncthreads();
        if (kb < qb) {
            uint32_t kbuf = KsU + (uint32_t)(((kb + 1) & 1) * K_HL) * 2;
            uint32_t vbuf = VsU + (uint32_t)(((kb + 1) & 1) * V_HL) * 2;
            const __half* kgn = kg + (size_t)(kb + 1) * 64 * QKV_N;
            const __half* vgn = vg + (size_t)(kb + 1) * 64 * QKV_N;
            #pragma unroll
            for (int t = 0; t < 4; t++) {
                int r = ldrow + t * 16;
                CP_ASYNC16(kbuf + (uint32_t)(r * ASTR + ldseg) * 2,
                           kgn + (size_t)r * QKV_N + ldseg);
                CP_ASYNC16(vbuf + (uint32_t)(r * ASTR + ldseg) * 2,
                           vgn + (size_t)r * QKV_N + ldseg);
            }
            CP_COMMIT();
        }
        uint32_t kcur = KsU + (uint32_t)((kb & 1) * K_HL) * 2;
        uint32_t vcur = VsU + (uint32_t)((kb & 1) * V_HL) * 2;

        float s[8][4];
        #pragma unroll
        for (int ni = 0; ni < 8; ni++)
            #pragma unroll
            for (int r = 0; r < 4; r++) s[ni][r] = 0.f;
        #pragma unroll
        for (int ks = 0; ks < 4; ks++) {
            uint32_t kbyte = (uint32_t)ks * 32;
            uint32_t a0, a1, a2, a3;
            LDSM4(a0, a1, a2, a3, QsU + qOff + kbyte);
            uint32_t bfr[8][2];
            #pragma unroll
            for (int j = 0; j < 4; j++)
                LDSM4(bfr[2 * j][0], bfr[2 * j][1], bfr[2 * j + 1][0], bfr[2 * j + 1][1],
                      kcur + kOff[j] + kbyte);
            #pragma unroll
            for (int ni = 0; ni < 8; ni++)
                MMA_F16(s[ni][0], s[ni][1], s[ni][2], s[ni][3],
                        a0, a1, a2, a3, bfr[ni][0], bfr[ni][1]);
        }
        #pragma unroll
        for (int ni = 0; ni < 8; ni++)
            #pragma unroll
            for (int r = 0; r < 4; r++) s[ni][r] *= 0.125f;
        if (kb == qb) {
            #pragma unroll
            for (int ni = 0; ni < 8; ni++) {
                int c0 = ni * 8 + tig * 2, c1 = c0 + 1;
                if (c0 > row_l0) s[ni][0] = -1e30f;
                if (c1 > row_l0) s[ni][1] = -1e30f;
                if (c0 > row_l1) s[ni][2] = -1e30f;
                if (c1 > row_l1) s[ni][3] = -1e30f;
            }
        }

        float rm0 = -1e30f, rm1 = -1e30f;
        #pragma unroll
        for (int ni = 0; ni < 8; ni++) {
            rm0 = fmaxf(rm0, fmaxf(s[ni][0], s[ni][1]));
            rm1 = fmaxf(rm1, fmaxf(s[ni][2], s[ni][3]));
        }
        rm0 = fmaxf(rm0, __shfl_xor_sync(0xffffffffu, rm0, 1));
        rm0 = fmaxf(rm0, __shfl_xor_sync(0xffffffffu, rm0, 2));
        rm1 = fmaxf(rm1, __shfl_xor_sync(0xffffffffu, rm1, 1));
        rm1 = fmaxf(rm1, __shfl_xor_sync(0xffffffffu, rm1, 2));
        float mn0 = fmaxf(m0, rm0), mn1 = fmaxf(m1, rm1);
        float al0 = __expf(m0 - mn0), al1 = __expf(m1 - mn1);
        float rs0 = 0.f, rs1 = 0.f;
        #pragma unroll
        for (int ni = 0; ni < 8; ni++) {
            s[ni][0] = __expf(s[ni][0] - mn0); rs0 += s[ni][0];
            s[ni][1] = __expf(s[ni][1] - mn0); rs0 += s[ni][1];
            s[ni][2] = __expf(s[ni][2] - mn1); rs1 += s[ni][2];
            s[ni][3] = __expf(s[ni][3] - mn1); rs1 += s[ni][3];
        }
        rs0 += __shfl_xor_sync(0xffffffffu, rs0, 1);
        rs0 += __shfl_xor_sync(0xffffffffu, rs0, 2);
        rs1 += __shfl_xor_sync(0xffffffffu, rs1, 1);
        rs1 += __shfl_xor_sync(0xffffffffu, rs1, 2);
        l0 = l0 * al0 + rs0; l1 = l1 * al1 + rs1;
        m0 = mn0; m1 = mn1;
        #pragma unroll
        for (int ni = 0; ni < 8; ni++) {
            oa[ni][0] *= al0; oa[ni][1] *= al0;
            oa[ni][2] *= al1; oa[ni][3] *= al1;
        }

        #pragma unroll
        for (int ni = 0; ni < 8; ni++) {
            int cc = ni * 8 + tig * 2;
            *(__half2*)(Ps + grp * ASTR + cc)       = __floats2half2_rn(s[ni][0], s[ni][1]);
            *(__half2*)(Ps + (grp + 8) * ASTR + cc) = __floats2half2_rn(s[ni][2], s[ni][3]);
        }
        __syncwarp();

        #pragma unroll
        for (int ks = 0; ks < 4; ks++) {
            uint32_t a0, a1, a2, a3;
            LDSM4(a0, a1, a2, a3, PsU + pOff + (uint32_t)ks * 32);
            uint32_t vrow = (uint32_t)(ks * 16 * ASTR) * 2;
            uint32_t bfr[8][2];
            #pragma unroll
            for (int j = 0; j < 4; j++)
                LDSM4T(bfr[2 * j][0], bfr[2 * j][1], bfr[2 * j + 1][0], bfr[2 * j + 1][1],
                       vcur + vrow + vOff[j]);
            #pragma unroll
            for (int ni = 0; ni < 8; ni++)
                MMA_F16(oa[ni][0], oa[ni][1], oa[ni][2], oa[ni][3],
                        a0, a1, a2, a3, bfr[ni][0], bfr[ni][1]);
        }
        __syncwarp();
    }

    float inv0 = 1.f / l0, inv1 = 1.f / l1;
    size_t r0 = baseo + (size_t)(qb * 64 + row_l0) * D_MODEL;
    size_t r1 = baseo + (size_t)(qb * 64 + row_l1) * D_MODEL;
    #pragma unroll
    for (int ni = 0; ni < 8; ni++) {
        int cc = ni * 8 + tig * 2;
        *(__half2*)(o + r0 + cc) = __floats2half2_rn(oa[ni][0] * inv0, oa[ni][1] * inv0);
        *(__half2*)(o + r1 + cc) = __floats2half2_rn(oa[ni][2] * inv1, oa[ni][3] * inv1);
    }
}

// ---------------- launch ----------------
extern "C" void kernel_launch(void* const* d_in, const int* in_sizes, int n_in,
                              void* d_out, int out_size)
{
    const float* x  = (const float*)d_in[0];
    const float* Wq = (const float*)d_in[1];
    const float* Wk = (const float*)d_in[2];
    const float* Wv = (const float*)d_in[3];
    const float* Wo = (const float*)d_in[4];
    const float* W1 = (const float*)d_in[5];
    const float* b1 = (const float*)d_in[6];
    const float* W2 = (const float*)d_in[7];
    const float* b2 = (const float*)d_in[8];
    const float* g1 = (const float*)d_in[9];
    const float* g2 = (const float*)d_in[10];
    float* out = (float*)d_out;

    __half *xn, *qkv, *attn, *hn, *f1, *wqkvT, *woT, *w1T, *w2T;
    float* x2;
    cudaGetSymbolAddress((void**)&xn,    g_xn_h);
    cudaGetSymbolAddress((void**)&qkv,   g_qkv_h);
    cudaGetSymbolAddress((void**)&attn,  g_attn_h);
    cudaGetSymbolAddress((void**)&x2,    g_x2);
    cudaGetSymbolAddress((void**)&hn,    g_hn_h);
    cudaGetSymbolAddress((void**)&f1,    g_f1_h);
    cudaGetSymbolAddress((void**)&wqkvT, g_wqkvT);
    cudaGetSymbolAddress((void**)&woT,   g_woT);
    cudaGetSymbolAddress((void**)&w1T,   g_w1T);
    cudaGetSymbolAddress((void**)&w2T,   g_w2T);

    cudaFuncSetAttribute(gemm_h<false, false, false, true>,
                         cudaFuncAttributeMaxDynamicSharedMemorySize, GEMM_SMEM);
    cudaFuncSetAttribute(gemm_h<false, false, true, false>,
                         cudaFuncAttributeMaxDynamicSharedMemorySize, GEMM_SMEM);
    cudaFuncSetAttribute(gemm_h<true, true, false, true>,
                         cudaFuncAttributeMaxDynamicSharedMemorySize, GEMM_SMEM);
    cudaFuncSetAttribute(gemm_h<true, false, true, false>,
                         cudaFuncAttributeMaxDynamicSharedMemorySize, GEMM_SMEM);
    cudaFuncSetAttribute(attn_h, cudaFuncAttributeMaxDynamicSharedMemorySize, ATTN_SMEM);

    transpose_sq <<<dim3(32, 32, 4), 256>>>(Wq, Wk, Wv, Wo, wqkvT, woT);
    transpose_ffn<<<dim3(128, 32, 2), 256>>>(W1, W2, w1T, w2T);
    rmsnorm_h<<<NTOK, 256>>>(x, g1, xn);
    gemm_h<false, false, false, true><<<dim3(QKV_N / 128, NTOK / 128), 256, GEMM_SMEM>>>(
        xn, wqkvT, nullptr, nullptr, qkv, NTOK, QKV_N, D_MODEL);
    attn_h<<<dim3(T_SEQ / 64, NH, BATCH), 128, ATTN_SMEM>>>(qkv, attn);
    gemm_h<false, false, true, false><<<dim3(D_MODEL / 128, NTOK / 128), 256, GEMM_SMEM>>>(
        attn, woT, nullptr, x, x2, NTOK, D_MODEL, D_MODEL);
    rmsnorm_h<<<NTOK, 256>>>(x2, g2, hn);
    gemm_h<true, true, false, true><<<dim3(D_FF / 128, NTOK / 128), 256, GEMM_SMEM>>>(
        hn, w1T, b1, nullptr, f1, NTOK, D_FF, D_MODEL);
    gemm_h<true, false, true, false><<<dim3(D_MODEL / 128, NTOK / 128), 256, GEMM_SMEM>>>(
        f1, w2T, b2, x2, out, NTOK, D_MODEL, D_FF);
}

// round 8
// speedup vs baseline: 6.6384x; 1.0389x over previous
#include <cuda_runtime.h>
#include <cuda_fp16.h>
#include <math.h>
#include <cstdint>

#define D_MODEL 1024
#define T_SEQ   2048
#define BATCH   2
#define NTOK    (BATCH * T_SEQ)   // 4096
#define D_FF    4096
#define NH      16
#define DH      64
#define QKV_N   3072

// ---------------- scratch (no allocations allowed) ----------------
__device__ __half g_xn_h  [NTOK * D_MODEL];
__device__ __half g_qkv_h [NTOK * QKV_N];
__device__ __half g_attn_h[NTOK * D_MODEL];
__device__ float  g_x2    [NTOK * D_MODEL];
__device__ __half g_hn_h  [NTOK * D_MODEL];
__device__ __half g_f1_h  [NTOK * D_FF];
__device__ __half g_wqkvT [QKV_N * D_MODEL];
__device__ __half g_woT   [D_MODEL * D_MODEL];
__device__ __half g_w1T   [D_FF * D_MODEL];
__device__ __half g_w2T   [D_MODEL * D_FF];

__device__ __forceinline__ uint32_t smem_u32(const void* p) {
    uint32_t a;
    asm("{ .reg .u64 t; cvta.to.shared.u64 t, %1; cvt.u32.u64 %0, t; }" : "=r"(a) : "l"(p));
    return a;
}
#define CP_ASYNC16(dst, src) \
    asm volatile("cp.async.cg.shared.global [%0], [%1], 16;" :: "r"(dst), "l"(src))
#define CP_COMMIT() asm volatile("cp.async.commit_group;")
#define CP_WAIT0()  asm volatile("cp.async.wait_group 0;")
#define CP_WAIT1()  asm volatile("cp.async.wait_group 1;")

#define MMA_F16(c0, c1, c2, c3, a0, a1, a2, a3, b0, b1) \
    asm volatile( \
        "mma.sync.aligned.m16n8k16.row.col.f32.f16.f16.f32 " \
        "{%0,%1,%2,%3}, {%4,%5,%6,%7}, {%8,%9}, {%0,%1,%2,%3};" \
        : "+f"(c0), "+f"(c1), "+f"(c2), "+f"(c3) \
        : "r"(a0), "r"(a1), "r"(a2), "r"(a3), "r"(b0), "r"(b1))

#define LDSM4(r0, r1, r2, r3, a) \
    asm volatile("ldmatrix.sync.aligned.m8n8.x4.shared.b16 {%0,%1,%2,%3}, [%4];" \
        : "=r"(r0), "=r"(r1), "=r"(r2), "=r"(r3) : "r"(a))
#define LDSM4T(r0, r1, r2, r3, a) \
    asm volatile("ldmatrix.sync.aligned.m8n8.x4.trans.shared.b16 {%0,%1,%2,%3}, [%4];" \
        : "=r"(r0), "=r"(r1), "=r"(r2), "=r"(r3) : "r"(a))

// ---------------- fused weight transposes: W[K][N] -> WT[N][K] (fp16) ----------------
__device__ __forceinline__ void trans_tile(
    const float* __restrict__ W, __half* __restrict__ WT, int K, int N, int n0, int k0)
{
    __shared__ float t[32][33];
    int tx = threadIdx.x & 31, ty = threadIdx.x >> 5;   // 32x8
    #pragma unroll
    for (int i = 0; i < 32; i += 8)
        t[ty + i][tx] = W[(size_t)(k0 + ty + i) * N + n0 + tx];
    __syncthreads();
    #pragma unroll
    for (int i = 0; i < 32; i += 8)
        WT[(size_t)(n0 + ty + i) * K + k0 + tx] = __float2half_rn(t[tx][ty + i]);
}

__global__ void __launch_bounds__(256) transpose_sq(
    const float* __restrict__ Wq, const float* __restrict__ Wk,
    const float* __restrict__ Wv, const float* __restrict__ Wo,
    __half* __restrict__ qkvT, __half* __restrict__ woT)
{
    int z = blockIdx.z;
    const float* src = (z == 0) ? Wq : (z == 1) ? Wk : (z == 2) ? Wv : Wo;
    __half* dst = (z < 3) ? (qkvT + (size_t)z * D_MODEL * D_MODEL) : woT;
    trans_tile(src, dst, D_MODEL, D_MODEL, blockIdx.x * 32, blockIdx.y * 32);
}

__global__ void __launch_bounds__(256) transpose_ffn(
    const float* __restrict__ W1, const float* __restrict__ W2,
    __half* __restrict__ w1T, __half* __restrict__ w2T)
{
    if (blockIdx.z == 0)
        trans_tile(W1, w1T, D_MODEL, D_FF, blockIdx.x * 32, blockIdx.y * 32);
    else
        trans_tile(W2, w2T, D_FF, D_MODEL, blockIdx.y * 32, blockIdx.x * 32);
}

// ---------------- RMSNorm (fp32 in, fp16 out) ----------------
__global__ void __launch_bounds__(256) rmsnorm_h(
    const float* __restrict__ x, const float* __restrict__ g, __half* __restrict__ y)
{
    int row = blockIdx.x;
    int tid = threadIdx.x;
    const float4* xr = (const float4*)(x + (size_t)row * D_MODEL);
    float4 v = xr[tid];
    float s = v.x * v.x + v.y * v.y + v.z * v.z + v.w * v.w;
    #pragma unroll
    for (int o = 16; o > 0; o >>= 1) s += __shfl_xor_sync(0xffffffffu, s, o);
    __shared__ float red[8];
    if ((tid & 31) == 0) red[tid >> 5] = s;
    __syncthreads();
    float tot = red[0] + red[1] + red[2] + red[3] + red[4] + red[5] + red[6] + red[7];
    float inv = rsqrtf(tot * (1.0f / D_MODEL) + 1e-6f);
    float4 gv = ((const float4*)g)[tid];
    __half2* yp = (__half2*)(y + (size_t)row * D_MODEL + tid * 4);
    yp[0] = __floats2half2_rn(v.x * inv * gv.x, v.y * inv * gv.y);
    yp[1] = __floats2half2_rn(v.z * inv * gv.z, v.w * inv * gv.w);
}

// ---------------- fp16 mma GEMM: 3-stage cp.async + register-pipelined frags ----------------
// Block 128x128, 8 warps (2M x 4N), warp 64x32; K-chunk 64 = 4 k16 steps.
#define KC 64
#define HSTR 72
#define STAGE_HL (128 * HSTR)            // halfs per operand per stage
#define STAGE_B  (STAGE_HL * 2)          // 18,432 bytes
#define GEMM_SMEM (3 * 2 * STAGE_B)      // 110,592 bytes

template<bool BIAS, bool GELU_ACT, bool RES, bool HOUT>
__global__ void __launch_bounds__(256) gemm_h(
    const __half* __restrict__ A, const __half* __restrict__ BT,
    const float* __restrict__ bias, const float* __restrict__ res,
    void* __restrict__ Cv, int M, int N, int K)
{
    extern __shared__ __half smh[];
    uint32_t AsU = smem_u32(smh);
    uint32_t BsU = AsU + 3 * STAGE_B;

    int tid = threadIdx.x;
    int lane = tid & 31, wid = tid >> 5;
    int warpM = (wid & 1) * 64;
    int warpN = (wid >> 1) * 32;
    int grp = lane >> 2, tig = lane & 3;
    int m8 = lane >> 3, l8 = lane & 7;
    int bn = blockIdx.x, bm = blockIdx.y;

    // loader: 128 rows x 64 halfs per operand per stage; 4 cp.async each
    int ldrow = tid >> 3;                // 0..31, step 32
    int ldseg = (tid & 7) << 3;          // 0..56 halfs
    const __half* Aptr = A  + (size_t)bm * 128 * K + (size_t)ldrow * K + ldseg;
    const __half* Bptr = BT + (size_t)bn * 128 * K + (size_t)ldrow * K + ldseg;
    uint32_t dA = AsU + (uint32_t)(ldrow * HSTR + ldseg) * 2;
    uint32_t dB = BsU + (uint32_t)(ldrow * HSTR + ldseg) * 2;

    // ldmatrix byte offsets
    uint32_t aOff[4], bOff[2];
    #pragma unroll
    for (int mi = 0; mi < 4; mi++)
        aOff[mi] = (uint32_t)((warpM + mi * 16 + (lane & 15)) * HSTR
                              + ((lane >> 4) << 3)) * 2;
    #pragma unroll
    for (int j = 0; j < 2; j++)
        bOff[j] = (uint32_t)((warpN + j * 16 + ((m8 >> 1) << 3) + l8) * HSTR
                              + ((m8 & 1) << 3)) * 2;

    float acc[4][4][4];
    #pragma unroll
    for (int mi = 0; mi < 4; mi++)
        #pragma unroll
        for (int ni = 0; ni < 4; ni++)
            #pragma unroll
            for (int r = 0; r < 4; r++) acc[mi][ni][r] = 0.f;

    int nch = K / KC;

    // prologue: stages 0 and 1
    #pragma unroll
    for (int s = 0; s < 2; s++) {
        uint32_t so = (uint32_t)s * STAGE_B;
        int k0 = s * KC;
        #pragma unroll
        for (int t = 0; t < 4; t++) {
            CP_ASYNC16(dA + so + (uint32_t)(t * 32 * HSTR) * 2,
                       Aptr + (size_t)t * 32 * K + k0);
            CP_ASYNC16(dB + so + (uint32_t)(t * 32 * HSTR) * 2,
                       Bptr + (size_t)t * 32 * K + k0);
        }
        CP_COMMIT();
    }

    // double-buffered register fragments
    uint32_t af[2][4][4], bf[2][4][2];

    int stage = 0;
    for (int c = 0; c < nch; c++) {
        if (c + 1 < nch) { CP_WAIT1(); } else { CP_WAIT0(); }
        __syncthreads();
        if (c + 2 < nch) {
            int sn = stage - 1; if (sn < 0) sn += 3;   // (c+2)%3 == (c-1)%3
            uint32_t so = (uint32_t)sn * STAGE_B;
            int k0 = (c + 2) * KC;
            #pragma unroll
            for (int t = 0; t < 4; t++) {
                CP_ASYNC16(dA + so + (uint32_t)(t * 32 * HSTR) * 2,
                           Aptr + (size_t)t * 32 * K + k0);
                CP_ASYNC16(dB + so + (uint32_t)(t * 32 * HSTR) * 2,
                           Bptr + (size_t)t * 32 * K + k0);
            }
            CP_COMMIT();
        }
        uint32_t abase = AsU + (uint32_t)stage * STAGE_B;
        uint32_t bbase = BsU + (uint32_t)stage * STAGE_B;

        // prime kk=0 fragments
        #pragma unroll
        for (int mi = 0; mi < 4; mi++)
            LDSM4(af[0][mi][0], af[0][mi][1], af[0][mi][2], af[0][mi][3],
                  abase + aOff[mi]);
        #pragma unroll
        for (int j = 0; j < 2; j++)
            LDSM4(bf[0][2 * j][0], bf[0][2 * j][1], bf[0][2 * j + 1][0], bf[0][2 * j + 1][1],
                  bbase + bOff[j]);

        #pragma unroll
        for (int kk = 0; kk < 4; kk++) {
            int cur = kk & 1, nxt = cur ^ 1;
            if (kk < 3) {
                uint32_t kb = (uint32_t)(kk + 1) * 32;
                #pragma unroll
                for (int mi = 0; mi < 4; mi++)
                    LDSM4(af[nxt][mi][0], af[nxt][mi][1], af[nxt][mi][2], af[nxt][mi][3],
                          abase + aOff[mi] + kb);
                #pragma unroll
                for (int j = 0; j < 2; j++)
                    LDSM4(bf[nxt][2 * j][0], bf[nxt][2 * j][1],
                          bf[nxt][2 * j + 1][0], bf[nxt][2 * j + 1][1],
                          bbase + bOff[j] + kb);
            }
            #pragma unroll
            for (int mi = 0; mi < 4; mi++)
                #pragma unroll
                for (int ni = 0; ni < 4; ni++)
                    MMA_F16(acc[mi][ni][0], acc[mi][ni][1], acc[mi][ni][2], acc[mi][ni][3],
                            af[cur][mi][0], af[cur][mi][1], af[cur][mi][2], af[cur][mi][3],
                            bf[cur][ni][0], bf[cur][ni][1]);
        }
        stage++; if (stage == 3) stage = 0;
    }

    #pragma unroll
    for (int mi = 0; mi < 4; mi++) {
        #pragma unroll
        for (int half = 0; half < 2; half++) {
            size_t r = (size_t)bm * 128 + warpM + mi * 16 + grp + half * 8;
            #pragma unroll
            for (int ni = 0; ni < 4; ni++) {
                int cg = bn * 128 + warpN + ni * 8 + tig * 2;
                float v0 = acc[mi][ni][half * 2 + 0];
                float v1 = acc[mi][ni][half * 2 + 1];
                if (BIAS) { v0 += bias[cg]; v1 += bias[cg + 1]; }
                if (GELU_ACT) {
                    v0 = 0.5f * v0 * (1.0f + erff(v0 * 0.70710678118654752f));
                    v1 = 0.5f * v1 * (1.0f + erff(v1 * 0.70710678118654752f));
                }
                size_t idx = r * (size_t)N + cg;
                if (RES) {
                    float2 r2 = *(const float2*)(res + idx);
                    v0 += r2.x; v1 += r2.y;
                }
                if (HOUT) {
                    *(__half2*)((__half*)Cv + idx) = __floats2half2_rn(v0, v1);
                } else {
                    float2 o2; o2.x = v0; o2.y = v1;
                    *(float2*)((float*)Cv + idx) = o2;
                }
            }
        }
    }
}

// ---------------- fp16 mma causal flash attention ----------------
#define ASTR 72
#define Q_HL (64 * ASTR)
#define K_HL (64 * ASTR)
#define V_HL (64 * ASTR)
#define P_HL (16 * ASTR)
#define ATTN_SMEM ((Q_HL + 2 * K_HL + 2 * V_HL + 4 * P_HL) * 2)

__global__ void __launch_bounds__(128) attn_h(
    const __half* __restrict__ qkv, __half* __restrict__ o)
{
    extern __shared__ __half smh[];
    __half* Qs = smh;
    __half* Ks = Qs + Q_HL;           // 2 buffers
    __half* Vs = Ks + 2 * K_HL;       // 2 buffers
    int tid = threadIdx.x;
    int lane = tid & 31, wid = tid >> 5;
    int grp = lane >> 2, tig = lane & 3;
    int m8 = lane >> 3, l8 = lane & 7;
    __half* Ps = Vs + 2 * V_HL + wid * P_HL;

    uint32_t QsU = smem_u32(Qs), KsU = smem_u32(Ks), VsU = smem_u32(Vs);
    uint32_t PsU = smem_u32(Ps);

    int qb = gridDim.x - 1 - blockIdx.x;   // heavy tiles first
    int h = blockIdx.y, b = blockIdx.z;
    size_t base  = (size_t)b * T_SEQ * QKV_N + h * DH;
    size_t baseo = (size_t)b * T_SEQ * D_MODEL + h * DH;
    const __half* qg = qkv + base;
    const __half* kg = qkv + base + D_MODEL;
    const __half* vg = qkv + base + 2 * D_MODEL;

    uint32_t qOff = (uint32_t)((wid * 16 + (lane & 15)) * ASTR + ((lane >> 4) << 3)) * 2;
    uint32_t kOff[4], vOff[4];
    #pragma unroll
    for (int j = 0; j < 4; j++) {
        kOff[j] = (uint32_t)((j * 16 + ((m8 >> 1) << 3) + l8) * ASTR
                             + ((m8 & 1) << 3)) * 2;
        vOff[j] = (uint32_t)((((m8 & 1) << 3) + l8) * ASTR
                             + j * 16 + ((m8 >> 1) << 3)) * 2;
    }
    uint32_t pOff = (uint32_t)((lane & 15) * ASTR + ((lane >> 4) << 3)) * 2;

    int ldrow = tid >> 3, ldseg = (tid & 7) << 3;   // 16 rows/step

    #pragma unroll
    for (int t = 0; t < 4; t++) {
        int r = ldrow + t * 16;
        CP_ASYNC16(QsU + (uint32_t)(r * ASTR + ldseg) * 2,
                   qg + (size_t)(qb * 64 + r) * QKV_N + ldseg);
    }
    #pragma unroll
    for (int t = 0; t < 4; t++) {
        int r = ldrow + t * 16;
        CP_ASYNC16(KsU + (uint32_t)(r * ASTR + ldseg) * 2, kg + (size_t)r * QKV_N + ldseg);
        CP_ASYNC16(VsU + (uint32_t)(r * ASTR + ldseg) * 2, vg + (size_t)r * QKV_N + ldseg);
    }
    CP_COMMIT();

    float m0 = -1e30f, m1 = -1e30f, l0 = 0.f, l1 = 0.f;
    float oa[8][4];
    #pragma unroll
    for (int ni = 0; ni < 8; ni++)
        #pragma unroll
        for (int r = 0; r < 4; r++) oa[ni][r] = 0.f;

    int row_l0 = wid * 16 + grp;
    int row_l1 = row_l0 + 8;

    for (int kb = 0; kb <= qb; kb++) {
        CP_WAIT0();
        __syncthreads();
        if (kb < qb) {
            uint32_t kbuf = KsU + (uint32_t)(((kb + 1) & 1) * K_HL) * 2;
            uint32_t vbuf = VsU + (uint32_t)(((kb + 1) & 1) * V_HL) * 2;
            const __half* kgn = kg + (size_t)(kb + 1) * 64 * QKV_N;
            const __half* vgn = vg + (size_t)(kb + 1) * 64 * QKV_N;
            #pragma unroll
            for (int t = 0; t < 4; t++) {
                int r = ldrow + t * 16;
                CP_ASYNC16(kbuf + (uint32_t)(r * ASTR + ldseg) * 2,
                           kgn + (size_t)r * QKV_N + ldseg);
                CP_ASYNC16(vbuf + (uint32_t)(r * ASTR + ldseg) * 2,
                           vgn + (size_t)r * QKV_N + ldseg);
            }
            CP_COMMIT();
        }
        uint32_t kcur = KsU + (uint32_t)((kb & 1) * K_HL) * 2;
        uint32_t vcur = VsU + (uint32_t)((kb & 1) * V_HL) * 2;

        float s[8][4];
        #pragma unroll
        for (int ni = 0; ni < 8; ni++)
            #pragma unroll
            for (int r = 0; r < 4; r++) s[ni][r] = 0.f;
        #pragma unroll
        for (int ks = 0; ks < 4; ks++) {
            uint32_t kbyte = (uint32_t)ks * 32;
            uint32_t a0, a1, a2, a3;
            LDSM4(a0, a1, a2, a3, QsU + qOff + kbyte);
            uint32_t bfr[8][2];
            #pragma unroll
            for (int j = 0; j < 4; j++)
                LDSM4(bfr[2 * j][0], bfr[2 * j][1], bfr[2 * j + 1][0], bfr[2 * j + 1][1],
                      kcur + kOff[j] + kbyte);
            #pragma unroll
            for (int ni = 0; ni < 8; ni++)
                MMA_F16(s[ni][0], s[ni][1], s[ni][2], s[ni][3],
                        a0, a1, a2, a3, bfr[ni][0], bfr[ni][1]);
        }
        #pragma unroll
        for (int ni = 0; ni < 8; ni++)
            #pragma unroll
            for (int r = 0; r < 4; r++) s[ni][r] *= 0.125f;
        if (kb == qb) {
            #pragma unroll
            for (int ni = 0; ni < 8; ni++) {
                int c0 = ni * 8 + tig * 2, c1 = c0 + 1;
                if (c0 > row_l0) s[ni][0] = -1e30f;
                if (c1 > row_l0) s[ni][1] = -1e30f;
                if (c0 > row_l1) s[ni][2] = -1e30f;
                if (c1 > row_l1) s[ni][3] = -1e30f;
            }
        }

        float rm0 = -1e30f, rm1 = -1e30f;
        #pragma unroll
        for (int ni = 0; ni < 8; ni++) {
            rm0 = fmaxf(rm0, fmaxf(s[ni][0], s[ni][1]));
            rm1 = fmaxf(rm1, fmaxf(s[ni][2], s[ni][3]));
        }
        rm0 = fmaxf(rm0, __shfl_xor_sync(0xffffffffu, rm0, 1));
        rm0 = fmaxf(rm0, __shfl_xor_sync(0xffffffffu, rm0, 2));
        rm1 = fmaxf(rm1, __shfl_xor_sync(0xffffffffu, rm1, 1));
        rm1 = fmaxf(rm1, __shfl_xor_sync(0xffffffffu, rm1, 2));
        float mn0 = fmaxf(m0, rm0), mn1 = fmaxf(m1, rm1);
        float al0 = __expf(m0 - mn0), al1 = __expf(m1 - mn1);
        float rs0 = 0.f, rs1 = 0.f;
        #pragma unroll
        for (int ni = 0; ni < 8; ni++) {
            s[ni][0] = __expf(s[ni][0] - mn0); rs0 += s[ni][0];
            s[ni][1] = __expf(s[ni][1] - mn0); rs0 += s[ni][1];
            s[ni][2] = __expf(s[ni][2] - mn1); rs1 += s[ni][2];
            s[ni][3] = __expf(s[ni][3] - mn1); rs1 += s[ni][3];
        }
        rs0 += __shfl_xor_sync(0xffffffffu, rs0, 1);
        rs0 += __shfl_xor_sync(0xffffffffu, rs0, 2);
        rs1 += __shfl_xor_sync(0xffffffffu, rs1, 1);
        rs1 += __shfl_xor_sync(0xffffffffu, rs1, 2);
        l0 = l0 * al0 + rs0; l1 = l1 * al1 + rs1;
        m0 = mn0; m1 = mn1;
        #pragma unroll
        for (int ni = 0; ni < 8; ni++) {
            oa[ni][0] *= al0; oa[ni][1] *= al0;
            oa[ni][2] *= al1; oa[ni][3] *= al1;
        }

        #pragma unroll
        for (int ni = 0; ni < 8; ni++) {
            int cc = ni * 8 + tig * 2;
            *(__half2*)(Ps + grp * ASTR + cc)       = __floats2half2_rn(s[ni][0], s[ni][1]);
            *(__half2*)(Ps + (grp + 8) * ASTR + cc) = __floats2half2_rn(s[ni][2], s[ni][3]);
        }
        __syncwarp();

        #pragma unroll
        for (int ks = 0; ks < 4; ks++) {
            uint32_t a0, a1, a2, a3;
            LDSM4(a0, a1, a2, a3, PsU + pOff + (uint32_t)ks * 32);
            uint32_t vrow = (uint32_t)(ks * 16 * ASTR) * 2;
            uint32_t bfr[8][2];
            #pragma unroll
            for (int j = 0; j < 4; j++)
                LDSM4T(bfr[2 * j][0], bfr[2 * j][1], bfr[2 * j + 1][0], bfr[2 * j + 1][1],
                       vcur + vrow + vOff[j]);
            #pragma unroll
            for (int ni = 0; ni < 8; ni++)
                MMA_F16(oa[ni][0], oa[ni][1], oa[ni][2], oa[ni][3],
                        a0, a1, a2, a3, bfr[ni][0], bfr[ni][1]);
        }
        __syncwarp();
    }

    float inv0 = 1.f / l0, inv1 = 1.f / l1;
    size_t r0 = baseo + (size_t)(qb * 64 + row_l0) * D_MODEL;
    size_t r1 = baseo + (size_t)(qb * 64 + row_l1) * D_MODEL;
    #pragma unroll
    for (int ni = 0; ni < 8; ni++) {
        int cc = ni * 8 + tig * 2;
        *(__half2*)(o + r0 + cc) = __floats2half2_rn(oa[ni][0] * inv0, oa[ni][1] * inv0);
        *(__half2*)(o + r1 + cc) = __floats2half2_rn(oa[ni][2] * inv1, oa[ni][3] * inv1);
    }
}

// ---------------- launch ----------------
extern "C" void kernel_launch(void* const* d_in, const int* in_sizes, int n_in,
                              void* d_out, int out_size)
{
    const float* x  = (const float*)d_in[0];
    const float* Wq = (const float*)d_in[1];
    const float* Wk = (const float*)d_in[2];
    const float* Wv = (const float*)d_in[3];
    const float* Wo = (const float*)d_in[4];
    const float* W1 = (const float*)d_in[5];
    const float* b1 = (const float*)d_in[6];
    const float* W2 = (const float*)d_in[7];
    const float* b2 = (const float*)d_in[8];
    const float* g1 = (const float*)d_in[9];
    const float* g2 = (const float*)d_in[10];
    float* out = (float*)d_out;

    __half *xn, *qkv, *attn, *hn, *f1, *wqkvT, *woT, *w1T, *w2T;
    float* x2;
    cudaGetSymbolAddress((void**)&xn,    g_xn_h);
    cudaGetSymbolAddress((void**)&qkv,   g_qkv_h);
    cudaGetSymbolAddress((void**)&attn,  g_attn_h);
    cudaGetSymbolAddress((void**)&x2,    g_x2);
    cudaGetSymbolAddress((void**)&hn,    g_hn_h);
    cudaGetSymbolAddress((void**)&f1,    g_f1_h);
    cudaGetSymbolAddress((void**)&wqkvT, g_wqkvT);
    cudaGetSymbolAddress((void**)&woT,   g_woT);
    cudaGetSymbolAddress((void**)&w1T,   g_w1T);
    cudaGetSymbolAddress((void**)&w2T,   g_w2T);

    cudaFuncSetAttribute(gemm_h<false, false, false, true>,
                         cudaFuncAttributeMaxDynamicSharedMemorySize, GEMM_SMEM);
    cudaFuncSetAttribute(gemm_h<false, false, true, false>,
                         cudaFuncAttributeMaxDynamicSharedMemorySize, GEMM_SMEM);
    cudaFuncSetAttribute(gemm_h<true, true, false, true>,
                         cudaFuncAttributeMaxDynamicSharedMemorySize, GEMM_SMEM);
    cudaFuncSetAttribute(gemm_h<true, false, true, false>,
                         cudaFuncAttributeMaxDynamicSharedMemorySize, GEMM_SMEM);
    cudaFuncSetAttribute(attn_h, cudaFuncAttributeMaxDynamicSharedMemorySize, ATTN_SMEM);

    transpose_sq <<<dim3(32, 32, 4), 256>>>(Wq, Wk, Wv, Wo, wqkvT, woT);
    transpose_ffn<<<dim3(128, 32, 2), 256>>>(W1, W2, w1T, w2T);
    rmsnorm_h<<<NTOK, 256>>>(x, g1, xn);
    gemm_h<false, false, false, true><<<dim3(QKV_N / 128, NTOK / 128), 256, GEMM_SMEM>>>(
        xn, wqkvT, nullptr, nullptr, qkv, NTOK, QKV_N, D_MODEL);
    attn_h<<<dim3(T_SEQ / 64, NH, BATCH), 128, ATTN_SMEM>>>(qkv, attn);
    gemm_h<false, false, true, false><<<dim3(D_MODEL / 128, NTOK / 128), 256, GEMM_SMEM>>>(
        attn, woT, nullptr, x, x2, NTOK, D_MODEL, D_MODEL);
    rmsnorm_h<<<NTOK, 256>>>(x2, g2, hn);
    gemm_h<true, true, false, true><<<dim3(D_FF / 128, NTOK / 128), 256, GEMM_SMEM>>>(
        hn, w1T, b1, nullptr, f1, NTOK, D_FF, D_MODEL);
    gemm_h<true, false, true, false><<<dim3(D_MODEL / 128, NTOK / 128), 256, GEMM_SMEM>>>(
        f1, w2T, b2, x2, out, NTOK, D_MODEL, D_FF);
}